// round 12
// baseline (speedup 1.0000x reference)
#include <cuda_runtime.h>
#include <cstdint>
#include <cstddef>

#define BATCH   256
#define SEQ     64
#define INPUT   512
#define HIDDEN  1024
#define CLASSES 1000
#define SB      (SEQ * BATCH)   // 16384
#define G4      (4 * HIDDEN)    // 4096
#define REC_CTAS 128u

// ---------------------------------------------------------------------------
// Scratch (device globals — no allocations allowed)
// ---------------------------------------------------------------------------
__device__ float g_X  [SB * INPUT];
__device__ float g_Z  [(size_t)SB * G4];
__device__ float g_H1 [(SEQ + 1) * BATCH * HIDDEN];
__device__ float g_h2 [2 * BATCH * HIDDEN];
__device__ float g_W1r[(size_t)G4 * INPUT];
__device__ float g_U1T[(size_t)G4 * HIDDEN];
__device__ float g_W2r[(size_t)G4 * HIDDEN];
__device__ float g_U2T[(size_t)G4 * HIDDEN];
__device__ float g_b1r[G4];
__device__ float g_b2r[G4];
__device__ unsigned g_bar1[SEQ];
__device__ unsigned g_bar2[SEQ];

// ---------------------------------------------------------------------------
// Helpers
// ---------------------------------------------------------------------------
__device__ __forceinline__ uint32_t smem_to_u32(const void* p) {
    uint32_t a;
    asm("{ .reg .u64 t; cvta.to.shared.u64 t, %1; cvt.u32.u64 %0, t; }"
        : "=r"(a) : "l"(p));
    return a;
}

__device__ __forceinline__ float to_tf32(float x) {
    uint32_t r;
    asm("cvt.rna.tf32.f32 %0, %1;" : "=r"(r) : "f"(x));
    return __uint_as_float(r);
}

__device__ __forceinline__ void cp_async16(uint32_t smem_dst, const void* gmem_src) {
    asm volatile("cp.async.cg.shared.global [%0], [%1], 16;\n" :: "r"(smem_dst), "l"(gmem_src));
}

__device__ __forceinline__ void mma_tf32_16n8k8(float* d, const uint32_t* a, const uint32_t* b) {
    asm volatile(
        "mma.sync.aligned.m16n8k8.row.col.f32.tf32.tf32.f32 "
        "{%0,%1,%2,%3}, {%4,%5,%6,%7}, {%8,%9}, {%0,%1,%2,%3};"
        : "+f"(d[0]), "+f"(d[1]), "+f"(d[2]), "+f"(d[3])
        : "r"(a[0]), "r"(a[1]), "r"(a[2]), "r"(a[3]), "r"(b[0]), "r"(b[1]));
}

#define LDSM_X4(r0, r1, r2, r3, addr) \
    asm volatile("ldmatrix.sync.aligned.m8n8.x4.shared.b16 {%0,%1,%2,%3}, [%4];" \
        : "=r"(r0), "=r"(r1), "=r"(r2), "=r"(r3) : "r"(addr))

__device__ __forceinline__ float sigf(float x) { return 1.f / (1.f + expf(-x)); }

// ---------------------------------------------------------------------------
// Big GEMM v2 (bias epilogue): C[M,N] = A[M,K] @ Bt[N,K]^T + bias
// 512 threads / 16 warps (4m x 4n, warp tile 32x32, MT=2/NT=4).
// BM=BN=128, BK=64, PAD=68, 3-stage cp.async, one sync per k-tile.
// 209KB smem -> 1 CTA/SM, 4 warps/SMSP (tuned mainloop from rec_layer).
// ---------------------------------------------------------------------------
template<int KT>
__global__ void __launch_bounds__(512, 1)
mma_gemm_bias(const float* __restrict__ A, int lda,
              const float* __restrict__ Bt,
              const float* __restrict__ bias,
              float* __restrict__ C)
{
    constexpr int BM = 128, BN = 128, BK = 64, PAD = 68;
    constexpr int MT = 2, NT = 4;
    constexpr int SFL = (BM + BN) * PAD;     // 17408 floats / 69632 B per stage

    extern __shared__ float sm[];
    const uint32_t sbase = smem_to_u32(sm);

    const int tid  = threadIdx.x;
    const int wid  = tid >> 5;               // 0..15
    const int lane = tid & 31;
    const int wm0  = (wid >> 2) * 32;        // 4 m-groups of 32 rows
    const int wn0  = (wid & 3) * 32;         // 4 n-groups of 32 cols
    const int m0   = blockIdx.y * BM;
    const int n0   = blockIdx.x * BN;
    const int K    = KT * BK;
    const int r    = lane >> 2;
    const int cq   = lane & 3;
    const int l8   = lane & 7;
    const int sid  = lane >> 3;

    uint32_t a_off[MT], b_off[2];
    #pragma unroll
    for (int mt = 0; mt < MT; mt++)
        a_off[mt] = (uint32_t)(((wm0 + mt * 16 + (sid & 1) * 8 + l8) * PAD
                                + (sid >> 1) * 4) * 4);
    #pragma unroll
    for (int p = 0; p < 2; p++)
        b_off[p] = (uint32_t)(((BM + wn0 + p * 16 + (sid >> 1) * 8 + l8) * PAD
                                + (sid & 1) * 4) * 4);

    float acc[MT][NT][4] = {};

    auto load_stage = [&](int kt) {
        const uint32_t dst = sbase + (uint32_t)(kt % 3) * (SFL * 4);
        const float* Ag = A  + (size_t)m0 * lda + kt * BK;
        const float* Bg = Bt + (size_t)n0 * K   + kt * BK;
        // A: 128 rows x 16 chunks of 16B = 2048 chunks
        #pragma unroll
        for (int i = 0; i < 4; i++) {
            int cid = tid + i * 512;
            int row = cid >> 4, c = cid & 15;
            cp_async16(dst + (uint32_t)(row * PAD * 4) + c * 16,
                       Ag + (size_t)row * lda + c * 4);
        }
        // B: 128 rows x 16 chunks = 2048 chunks
        #pragma unroll
        for (int i = 0; i < 4; i++) {
            int cid = tid + i * 512;
            int row = cid >> 4, c = cid & 15;
            cp_async16(dst + (uint32_t)((BM + row) * PAD * 4) + c * 16,
                       Bg + (size_t)row * K + c * 4);
        }
        asm volatile("cp.async.commit_group;\n");
    };

    load_stage(0);
    if (KT > 1) load_stage(1);

    #pragma unroll 1
    for (int kt = 0; kt < KT; kt++) {
        if (kt < KT - 1) asm volatile("cp.async.wait_group 1;\n");
        else             asm volatile("cp.async.wait_group 0;\n");
        __syncthreads();

        if (kt + 2 < KT) load_stage(kt + 2);

        const uint32_t stg = sbase + (uint32_t)(kt % 3) * (SFL * 4);

        #pragma unroll
        for (int ks = 0; ks < 8; ks++) {
            uint32_t af[MT][4], bf[NT][2];
            #pragma unroll
            for (int mt = 0; mt < MT; mt++)
                LDSM_X4(af[mt][0], af[mt][1], af[mt][2], af[mt][3],
                        stg + a_off[mt] + ks * 32);
            #pragma unroll
            for (int p = 0; p < 2; p++) {
                uint32_t q0, q1, q2, q3;
                LDSM_X4(q0, q1, q2, q3, stg + b_off[p] + ks * 32);
                bf[2 * p][0] = q0; bf[2 * p][1] = q1;
                bf[2 * p + 1][0] = q2; bf[2 * p + 1][1] = q3;
            }
            #pragma unroll
            for (int mt = 0; mt < MT; mt++)
                #pragma unroll
                for (int nt = 0; nt < NT; nt++)
                    mma_tf32_16n8k8(acc[mt][nt], af[mt], bf[nt]);
        }
    }

    #pragma unroll
    for (int mt = 0; mt < MT; mt++) {
        #pragma unroll
        for (int nt = 0; nt < NT; nt++) {
            const int row  = m0 + wm0 + mt * 16 + r;
            const int colb = n0 + wn0 + nt * 8 + cq * 2;
            float2 bv = *reinterpret_cast<const float2*>(bias + colb);
            float2 o01 = { acc[mt][nt][0] + bv.x, acc[mt][nt][1] + bv.y };
            float2 o23 = { acc[mt][nt][2] + bv.x, acc[mt][nt][3] + bv.y };
            *reinterpret_cast<float2*>(C + (size_t)row * G4 + colb)       = o01;
            *reinterpret_cast<float2*>(C + (size_t)(row + 8) * G4 + colb) = o23;
        }
    }
}

// ---------------------------------------------------------------------------
// Persistent recurrence v6 (UNCHANGED from round 11 — protected win).
// 512 threads: warps 0-7 consumers (4m x 2n, 32x32 tiles), warps 8-15 producers.
// ---------------------------------------------------------------------------
template<int L1>
__global__ void __launch_bounds__(512, 1)
rec_layer(const float* __restrict__ Uw,
          const float* __restrict__ Z,
          float* __restrict__ Hbuf,
          unsigned* __restrict__ bar)
{
    constexpr int BM = 128, BN = 64, BK = 64, PAD = 68, KT = 16;
    constexpr int MT = 2, NT = 4;
    constexpr int SFL  = (BM + BN) * PAD;
    constexpr int ZOFF = 3 * SFL;
    constexpr int ZPAD = 68;
    const size_t BH  = (size_t)BATCH * HIDDEN;
    const size_t BG4 = (size_t)BATCH * G4;

    extern __shared__ float sm[];
    const uint32_t sbase = smem_to_u32(sm);

    const int tid  = threadIdx.x;
    const int wid  = tid >> 5;
    const int lane = tid & 31;
    const bool prod = (wid >= 8);
    const int ptid = tid - 256;
    const int m0   = blockIdx.y * BM;
    const int n0   = blockIdx.x * BN;
    const int r    = lane >> 2;
    const int cq   = lane & 3;
    const int l8   = lane & 7;
    const int sid  = lane >> 3;

    const int wm0  = (wid >> 1) * 32;
    const int wn0  = (wid & 1) * 32;

    uint32_t a_off[MT], b_off[2];
    #pragma unroll
    for (int mt = 0; mt < MT; mt++)
        a_off[mt] = (uint32_t)(((wm0 + mt * 16 + (sid & 1) * 8 + l8) * PAD
                                + (sid >> 1) * 4) * 4);
    #pragma unroll
    for (int p = 0; p < 2; p++)
        b_off[p] = (uint32_t)(((BM + wn0 + p * 16 + (sid >> 1) * 8 + l8) * PAD
                                + (sid & 1) * 4) * 4);

    float creg[MT * NT * 2] = {};

    #pragma unroll 1
    for (int t = 0; t < SEQ; t++) {
        const float* A    = Hbuf + (size_t)(L1 ? t : (t & 1)) * BH;
        float*       Hout = Hbuf + (size_t)(L1 ? (t + 1) : ((t + 1) & 1)) * BH;
        const float* Zt   = Z + (size_t)t * BG4;

        float acc[MT][NT][4] = {};

        auto load_stage = [&](int kt, bool with_z) {
            const int s3 = kt % 3;
            const uint32_t dst = sbase + (uint32_t)s3 * (SFL * 4);
            const float* Ag = A  + (size_t)m0 * HIDDEN + kt * BK;
            const float* Bg = Uw + (size_t)n0 * HIDDEN + kt * BK;
            #pragma unroll
            for (int i = 0; i < 8; i++) {
                int cid = ptid + i * 256;
                int row = cid >> 4, c = cid & 15;
                cp_async16(dst + (uint32_t)(row * PAD * 4) + c * 16,
                           Ag + (size_t)row * HIDDEN + c * 4);
            }
            #pragma unroll
            for (int i = 0; i < 4; i++) {
                int cid = ptid + i * 256;
                int row = cid >> 4, c = cid & 15;
                cp_async16(dst + (uint32_t)((BM + row) * PAD * 4) + c * 16,
                           Bg + (size_t)row * HIDDEN + c * 4);
            }
            if (with_z) {
                #pragma unroll
                for (int i = 0; i < 8; i++) {
                    int cid = ptid + i * 256;
                    int row = cid >> 4, c = cid & 15;
                    cp_async16(sbase + (uint32_t)((ZOFF + row * ZPAD) * 4) + c * 16,
                               Zt + (size_t)(m0 + row) * G4 + n0 + c * 4);
                }
            }
            asm volatile("cp.async.commit_group;\n");
        };

        if (prod) {
            load_stage(0, false);
            load_stage(1, true);
        }

        #pragma unroll 1
        for (int kt = 0; kt < KT; kt++) {
            if (prod) {
                if (kt < KT - 1) asm volatile("cp.async.wait_group 1;\n");
                else             asm volatile("cp.async.wait_group 0;\n");
            }
            __syncthreads();

            if (prod) {
                if (kt + 2 < KT) load_stage(kt + 2, false);
            } else {
                const uint32_t stg = sbase + (uint32_t)(kt % 3) * (SFL * 4);
                #pragma unroll
                for (int ks = 0; ks < 8; ks++) {
                    uint32_t af[MT][4], bf[NT][2];
                    #pragma unroll
                    for (int mt = 0; mt < MT; mt++)
                        LDSM_X4(af[mt][0], af[mt][1], af[mt][2], af[mt][3],
                                stg + a_off[mt] + ks * 32);
                    #pragma unroll
                    for (int p = 0; p < 2; p++) {
                        uint32_t q0, q1, q2, q3;
                        LDSM_X4(q0, q1, q2, q3, stg + b_off[p] + ks * 32);
                        bf[2 * p][0] = q0; bf[2 * p][1] = q1;
                        bf[2 * p + 1][0] = q2; bf[2 * p + 1][1] = q3;
                    }
                    #pragma unroll
                    for (int mt = 0; mt < MT; mt++)
                        #pragma unroll
                        for (int nt = 0; nt < NT; nt++)
                            mma_tf32_16n8k8(acc[mt][nt], af[mt], bf[nt]);
                }
            }
        }

        if (!prod) {
            #pragma unroll
            for (int mt = 0; mt < MT; mt++) {
                #pragma unroll
                for (int nt = 0; nt < NT; nt++) {
                    const int rl   = wm0 + mt * 16 + r;
                    const int cl   = wn0 + nt * 8 + cq * 2;
                    float v0 = acc[mt][nt][0], v1 = acc[mt][nt][1];
                    float v2 = acc[mt][nt][2], v3 = acc[mt][nt][3];
                    float2 z01 = *reinterpret_cast<const float2*>(sm + ZOFF + rl * ZPAD + cl);
                    float2 z23 = *reinterpret_cast<const float2*>(sm + ZOFF + (rl + 8) * ZPAD + cl);
                    v0 += z01.x; v1 += z01.y; v2 += z23.x; v3 += z23.y;
                    float p0 = __shfl_xor_sync(0xffffffffu, v0, 1);
                    float p1 = __shfl_xor_sync(0xffffffffu, v1, 1);
                    float p2 = __shfl_xor_sync(0xffffffffu, v2, 1);
                    float p3 = __shfl_xor_sync(0xffffffffu, v3, 1);
                    if ((lane & 1) == 0) {
                        const int row = m0 + rl;
                        const int j   = (n0 + cl) >> 2;
                        const int ci  = (mt * NT + nt) * 2;
                        float cn = sigf(v1) * creg[ci] + sigf(v0) * tanhf(p0);
                        creg[ci] = cn;
                        Hout[(size_t)row * HIDDEN + j] = to_tf32(sigf(p1) * tanhf(cn));
                        float cn2 = sigf(v3) * creg[ci + 1] + sigf(v2) * tanhf(p2);
                        creg[ci + 1] = cn2;
                        Hout[(size_t)(row + 8) * HIDDEN + j] = to_tf32(sigf(p3) * tanhf(cn2));
                    }
                }
            }
        }

        if (t < SEQ - 1) {
            __syncthreads();
            if (tid == 0) {
                __threadfence();
                atomicAdd(&bar[t], 1u);
                volatile unsigned* p = bar + t;
                while (*p < REC_CTAS) { }
                __threadfence();
            }
            __syncthreads();
        }
    }
}

// ---------------------------------------------------------------------------
// Weight transpose + gate interleave: out[4j+g, k] = in[k, g*H + j]
// ---------------------------------------------------------------------------
__global__ void reorder_w_all(const float* __restrict__ W1, const float* __restrict__ U1,
                              const float* __restrict__ W2, const float* __restrict__ U2,
                              float* __restrict__ W1r, float* __restrict__ U1T,
                              float* __restrict__ W2r, float* __restrict__ U2T)
{
    __shared__ float tile[32][33];
    const int z  = blockIdx.z;
    const int mi = z >> 2, g = z & 3;
    const int K  = (mi == 0) ? INPUT : HIDDEN;
    const int k0 = blockIdx.x * 32;
    if (k0 >= K) return;
    const int j0 = blockIdx.y * 32;
    const float* in  = (mi == 0) ? W1 : (mi == 1) ? U1 : (mi == 2) ? W2 : U2;
    float*       out = (mi == 0) ? W1r : (mi == 1) ? U1T : (mi == 2) ? W2r : U2T;
    const int tx = threadIdx.x, ty = threadIdx.y;
    tile[ty][tx] = in[(size_t)(k0 + ty) * G4 + g * HIDDEN + j0 + tx];
    __syncthreads();
    out[(size_t)(4 * (j0 + ty) + g) * K + k0 + tx] = to_tf32(tile[tx][ty]);
}

// ---------------------------------------------------------------------------
// Misc init: bias reorder + state zero + barrier zero (one launch)
// ---------------------------------------------------------------------------
__global__ void misc_init(const float* __restrict__ b1, const float* __restrict__ b2,
                          float* __restrict__ b1r, float* __restrict__ b2r,
                          float* __restrict__ H1_0, float* __restrict__ h2_0,
                          unsigned* __restrict__ bar1, unsigned* __restrict__ bar2)
{
    int flat = blockIdx.x * blockDim.x + threadIdx.x;
    if (flat < G4)           b1r[flat] = b1[(flat & 3) * HIDDEN + (flat >> 2)];
    else if (flat < 2 * G4) { int m = flat - G4; b2r[m] = b2[(m & 3) * HIDDEN + (m >> 2)]; }
    if (flat < BATCH * HIDDEN) { H1_0[flat] = 0.f; h2_0[flat] = 0.f; }
    if (flat < SEQ) { bar1[flat] = 0u; bar2[flat] = 0u; }
}

// ---------------------------------------------------------------------------
// Pack x: [B, S, I] -> [S*B, I]  (row m = t*B + b), tf32-rounded
// ---------------------------------------------------------------------------
__global__ void pack_x_kernel(const float4* __restrict__ x, float4* __restrict__ xp) {
    int n = blockIdx.x * blockDim.x + threadIdx.x;
    const int I4 = INPUT / 4;
    int k = n % I4;
    int rr = n / I4;
    int b = rr % BATCH;
    int t = rr / BATCH;
    float4 v = x[((size_t)b * SEQ + t) * I4 + k];
    v.x = to_tf32(v.x); v.y = to_tf32(v.y); v.z = to_tf32(v.z); v.w = to_tf32(v.w);
    xp[n] = v;
}

// ---------------------------------------------------------------------------
// Final projection (M=256, N=1000, K=1024) — scalar fp32 (exact)
// ---------------------------------------------------------------------------
__global__ void final_proj_kernel(const float* __restrict__ A,
                                  const float* __restrict__ B,
                                  const float* __restrict__ bias,
                                  float* __restrict__ C)
{
    constexpr int BM = 64, BN = 64, BK = 16, TM = 4, TN = 4, TX = 16;
    __shared__ float As[BK][BM];
    __shared__ float Bs[BK][BN];
    const int tid  = threadIdx.x;
    const int tx   = tid % TX;
    const int ty   = tid / TX;
    const int brow = blockIdx.y * BM;
    const int bcol = blockIdx.x * BN;
    float acc[TM][TN] = {};

    for (int kt = 0; kt < HIDDEN; kt += BK) {
        {
            int ar = tid / (BK / 4);
            int ak = (tid % (BK / 4)) * 4;
            float4 v = *reinterpret_cast<const float4*>(A + (size_t)(brow + ar) * HIDDEN + kt + ak);
            As[ak + 0][ar] = v.x; As[ak + 1][ar] = v.y; As[ak + 2][ar] = v.z; As[ak + 3][ar] = v.w;
        }
        {
            int bk = tid / (BN / 4);
            int bn = (tid % (BN / 4)) * 4;
            int col = bcol + bn;
            const float* src = B + (size_t)(kt + bk) * CLASSES + col;
            Bs[bk][bn + 0] = (col + 0 < CLASSES) ? src[0] : 0.f;
            Bs[bk][bn + 1] = (col + 1 < CLASSES) ? src[1] : 0.f;
            Bs[bk][bn + 2] = (col + 2 < CLASSES) ? src[2] : 0.f;
            Bs[bk][bn + 3] = (col + 3 < CLASSES) ? src[3] : 0.f;
        }
        __syncthreads();
        #pragma unroll
        for (int k = 0; k < BK; k++) {
            float ra[TM], rb[TN];
            #pragma unroll
            for (int i = 0; i < TM; i++) ra[i] = As[k][ty * TM + i];
            #pragma unroll
            for (int j = 0; j < TN; j++) rb[j] = Bs[k][tx * TN + j];
            #pragma unroll
            for (int i = 0; i < TM; i++)
                #pragma unroll
                for (int j = 0; j < TN; j++)
                    acc[i][j] += ra[i] * rb[j];
        }
        __syncthreads();
    }
    #pragma unroll
    for (int i = 0; i < TM; i++) {
        int rr = brow + ty * TM + i;
        #pragma unroll
        for (int j = 0; j < TN; j++) {
            int col = bcol + tx * TN + j;
            if (col < CLASSES)
                C[(size_t)rr * CLASSES + col] = acc[i][j] + bias[col];
        }
    }
}

// ---------------------------------------------------------------------------
// Launch (8 nodes; launch #4 = mma_gemm_bias<8> for ncu capture)
// ---------------------------------------------------------------------------
extern "C" void kernel_launch(void* const* d_in, const int* in_sizes, int n_in,
                              void* d_out, int out_size)
{
    const float* x  = (const float*)d_in[0];
    const float* W1 = (const float*)d_in[1];
    const float* U1 = (const float*)d_in[2];
    const float* b1 = (const float*)d_in[3];
    const float* W2 = (const float*)d_in[4];
    const float* U2 = (const float*)d_in[5];
    const float* b2 = (const float*)d_in[6];
    const float* Wo = (const float*)d_in[7];
    const float* bo = (const float*)d_in[8];
    float* out = (float*)d_out;

    float *X, *Z, *H1, *h2, *W1r, *U1T, *W2r, *U2T, *b1r, *b2r;
    unsigned *bar1, *bar2;
    cudaGetSymbolAddress((void**)&X,   g_X);
    cudaGetSymbolAddress((void**)&Z,   g_Z);
    cudaGetSymbolAddress((void**)&H1,  g_H1);
    cudaGetSymbolAddress((void**)&h2,  g_h2);
    cudaGetSymbolAddress((void**)&W1r, g_W1r);
    cudaGetSymbolAddress((void**)&U1T, g_U1T);
    cudaGetSymbolAddress((void**)&W2r, g_W2r);
    cudaGetSymbolAddress((void**)&U2T, g_U2T);
    cudaGetSymbolAddress((void**)&b1r, g_b1r);
    cudaGetSymbolAddress((void**)&b2r, g_b2r);
    cudaGetSymbolAddress((void**)&bar1, g_bar1);
    cudaGetSymbolAddress((void**)&bar2, g_bar2);

    const int SMEM_BIG = 3 * (128 + 128) * 68 * 4;                    // 208896
    const int SMEM_REC = (3 * (128 + 64) * 68 + 128 * 68) * 4;        // 191488
    cudaFuncSetAttribute(mma_gemm_bias<8>,  cudaFuncAttributeMaxDynamicSharedMemorySize, SMEM_BIG);
    cudaFuncSetAttribute(mma_gemm_bias<16>, cudaFuncAttributeMaxDynamicSharedMemorySize, SMEM_BIG);
    cudaFuncSetAttribute(rec_layer<1>, cudaFuncAttributeMaxDynamicSharedMemorySize, SMEM_REC);
    cudaFuncSetAttribute(rec_layer<0>, cudaFuncAttributeMaxDynamicSharedMemorySize, SMEM_REC);

    const size_t BH = (size_t)BATCH * HIDDEN;

    // 1) pack X
    pack_x_kernel<<<SB * INPUT / 4 / 256, 256>>>((const float4*)x, (float4*)X);
    // 2) reorder weights
    reorder_w_all<<<dim3(32, 32, 16), dim3(32, 32)>>>(W1, U1, W2, U2, W1r, U1T, W2r, U2T);
    // 3) biases + state + barrier init
    misc_init<<<(BATCH * HIDDEN) / 256, 256>>>(b1, b2, b1r, b2r, H1, h2, bar1, bar2);
    // 4) Z = X @ W1r^T + b1r  (K=512, KT=8)   <-- ncu capture slot
    mma_gemm_bias<8><<<dim3(G4 / 128, SB / 128), 512, SMEM_BIG>>>(X, INPUT, W1r, b1r, Z);
    // 5) layer-1 recurrence
    rec_layer<1><<<dim3(64, 2), 512, SMEM_REC>>>(U1T, Z, H1, bar1);
    // 6) Z = H1[1..64] @ W2r^T + b2r  (K=1024, KT=16)
    mma_gemm_bias<16><<<dim3(G4 / 128, SB / 128), 512, SMEM_BIG>>>(H1 + BH, HIDDEN, W2r, b2r, Z);
    // 7) layer-2 recurrence
    rec_layer<0><<<dim3(64, 2), 512, SMEM_REC>>>(U2T, Z, h2, bar2);
    // 8) out = h2[0] @ Wo + bo
    final_proj_kernel<<<dim3((CLASSES + 63) / 64, BATCH / 64), 256>>>(h2, Wo, bo, out);
}

// round 13
// speedup vs baseline: 1.0810x; 1.0810x over previous
#include <cuda_runtime.h>
#include <cstdint>
#include <cstddef>

#define BATCH   256
#define SEQ     64
#define INPUT   512
#define HIDDEN  1024
#define CLASSES 1000
#define SB      (SEQ * BATCH)   // 16384
#define G4      (4 * HIDDEN)    // 4096
#define REC_CTAS 128u

// ---------------------------------------------------------------------------
// Scratch (device globals — no allocations allowed)
// ---------------------------------------------------------------------------
__device__ float g_X  [SB * INPUT];
__device__ float g_Z  [(size_t)SB * G4];
__device__ float g_H1 [(SEQ + 1) * BATCH * HIDDEN];
__device__ float g_h2 [2 * BATCH * HIDDEN];
__device__ float g_W1r[(size_t)G4 * INPUT];
__device__ float g_U1T[(size_t)G4 * HIDDEN];
__device__ float g_W2r[(size_t)G4 * HIDDEN];
__device__ float g_U2T[(size_t)G4 * HIDDEN];
__device__ float g_b1r[G4];
__device__ float g_b2r[G4];
__device__ unsigned g_bar1[SEQ];
__device__ unsigned g_bar2[SEQ];

// ---------------------------------------------------------------------------
// Helpers
// ---------------------------------------------------------------------------
__device__ __forceinline__ uint32_t smem_to_u32(const void* p) {
    uint32_t a;
    asm("{ .reg .u64 t; cvta.to.shared.u64 t, %1; cvt.u32.u64 %0, t; }"
        : "=r"(a) : "l"(p));
    return a;
}

__device__ __forceinline__ float to_tf32(float x) {
    uint32_t r;
    asm("cvt.rna.tf32.f32 %0, %1;" : "=r"(r) : "f"(x));
    return __uint_as_float(r);
}

__device__ __forceinline__ void cp_async16(uint32_t smem_dst, const void* gmem_src) {
    asm volatile("cp.async.cg.shared.global [%0], [%1], 16;\n" :: "r"(smem_dst), "l"(gmem_src));
}

__device__ __forceinline__ void mma_tf32_16n8k8(float* d, const uint32_t* a, const uint32_t* b) {
    asm volatile(
        "mma.sync.aligned.m16n8k8.row.col.f32.tf32.tf32.f32 "
        "{%0,%1,%2,%3}, {%4,%5,%6,%7}, {%8,%9}, {%0,%1,%2,%3};"
        : "+f"(d[0]), "+f"(d[1]), "+f"(d[2]), "+f"(d[3])
        : "r"(a[0]), "r"(a[1]), "r"(a[2]), "r"(a[3]), "r"(b[0]), "r"(b[1]));
}

#define LDSM_X4(r0, r1, r2, r3, addr) \
    asm volatile("ldmatrix.sync.aligned.m8n8.x4.shared.b16 {%0,%1,%2,%3}, [%4];" \
        : "=r"(r0), "=r"(r1), "=r"(r2), "=r"(r3) : "r"(addr))

__device__ __forceinline__ float sigf(float x) { return 1.f / (1.f + expf(-x)); }

// ---------------------------------------------------------------------------
// Big GEMM v3 (bias epilogue): C[M,N] = A[M,K] @ Bt[N,K]^T + bias
// 256 threads / 8 warps (2m x 4n, warp tile 64x32, MT=4/NT=4, 192B/mma).
// BM=BN=128, BK=32, PAD=36, 3-stage ring, ONE sync per k-tile.
// 110.6KB smem -> 2 CTAs/SM (epilogue/tail overlap preserved).
// ---------------------------------------------------------------------------
template<int KT>
__global__ void __launch_bounds__(256, 2)
mma_gemm_bias(const float* __restrict__ A, int lda,
              const float* __restrict__ Bt,
              const float* __restrict__ bias,
              float* __restrict__ C)
{
    constexpr int BM = 128, BN = 128, BK = 32, PAD = 36;
    constexpr int MT = 4, NT = 4;
    constexpr int SFL = (BM + BN) * PAD;     // 9216 floats / 36864 B per stage

    extern __shared__ float sm[];
    const uint32_t sbase = smem_to_u32(sm);

    const int tid  = threadIdx.x;
    const int wid  = tid >> 5;
    const int lane = tid & 31;
    const int wm0  = (wid >> 2) * 64;
    const int wn0  = (wid & 3) * 32;
    const int m0   = blockIdx.y * BM;
    const int n0   = blockIdx.x * BN;
    const int K    = KT * BK;
    const int r    = lane >> 2;
    const int cq   = lane & 3;
    const int l8   = lane & 7;
    const int sid  = lane >> 3;

    uint32_t a_off[MT], b_off[2];
    #pragma unroll
    for (int mt = 0; mt < MT; mt++)
        a_off[mt] = (uint32_t)(((wm0 + mt * 16 + (sid & 1) * 8 + l8) * PAD
                                + (sid >> 1) * 4) * 4);
    #pragma unroll
    for (int p = 0; p < 2; p++)
        b_off[p] = (uint32_t)(((BM + wn0 + p * 16 + (sid >> 1) * 8 + l8) * PAD
                                + (sid & 1) * 4) * 4);

    float acc[MT][NT][4] = {};

    auto load_stage = [&](int kt) {
        const uint32_t dst = sbase + (uint32_t)(kt % 3) * (SFL * 4);
        const float* Ag = A  + (size_t)m0 * lda + kt * BK;
        const float* Bg = Bt + (size_t)n0 * K   + kt * BK;
        // A: 128 rows x 8 chunks of 16B = 1024 chunks
        #pragma unroll
        for (int i = 0; i < 4; i++) {
            int cid = tid + i * 256;
            int row = cid >> 3, c = cid & 7;
            cp_async16(dst + (uint32_t)(row * PAD * 4) + c * 16,
                       Ag + (size_t)row * lda + c * 4);
        }
        // B: 128 rows x 8 chunks = 1024 chunks
        #pragma unroll
        for (int i = 0; i < 4; i++) {
            int cid = tid + i * 256;
            int row = cid >> 3, c = cid & 7;
            cp_async16(dst + (uint32_t)((BM + row) * PAD * 4) + c * 16,
                       Bg + (size_t)row * K + c * 4);
        }
        asm volatile("cp.async.commit_group;\n");
    };

    load_stage(0);
    if (KT > 1) load_stage(1);

    #pragma unroll 1
    for (int kt = 0; kt < KT; kt++) {
        if (kt < KT - 1) asm volatile("cp.async.wait_group 1;\n");
        else             asm volatile("cp.async.wait_group 0;\n");
        __syncthreads();     // stage kt ready; stage (kt+2)%3 drained (read in kt-1)

        if (kt + 2 < KT) load_stage(kt + 2);

        const uint32_t stg = sbase + (uint32_t)(kt % 3) * (SFL * 4);

        #pragma unroll
        for (int ks = 0; ks < 4; ks++) {
            uint32_t af[MT][4], bf[NT][2];
            #pragma unroll
            for (int mt = 0; mt < MT; mt++)
                LDSM_X4(af[mt][0], af[mt][1], af[mt][2], af[mt][3],
                        stg + a_off[mt] + ks * 32);
            #pragma unroll
            for (int p = 0; p < 2; p++) {
                uint32_t q0, q1, q2, q3;
                LDSM_X4(q0, q1, q2, q3, stg + b_off[p] + ks * 32);
                bf[2 * p][0] = q0; bf[2 * p][1] = q1;
                bf[2 * p + 1][0] = q2; bf[2 * p + 1][1] = q3;
            }
            #pragma unroll
            for (int mt = 0; mt < MT; mt++)
                #pragma unroll
                for (int nt = 0; nt < NT; nt++)
                    mma_tf32_16n8k8(acc[mt][nt], af[mt], bf[nt]);
        }
    }

    #pragma unroll
    for (int mt = 0; mt < MT; mt++) {
        #pragma unroll
        for (int nt = 0; nt < NT; nt++) {
            const int row  = m0 + wm0 + mt * 16 + r;
            const int colb = n0 + wn0 + nt * 8 + cq * 2;
            float2 bv = *reinterpret_cast<const float2*>(bias + colb);
            float2 o01 = { acc[mt][nt][0] + bv.x, acc[mt][nt][1] + bv.y };
            float2 o23 = { acc[mt][nt][2] + bv.x, acc[mt][nt][3] + bv.y };
            *reinterpret_cast<float2*>(C + (size_t)row * G4 + colb)       = o01;
            *reinterpret_cast<float2*>(C + (size_t)(row + 8) * G4 + colb) = o23;
        }
    }
}

// ---------------------------------------------------------------------------
// Persistent recurrence v6 (UNCHANGED from round 11 — protected win).
// 512 threads: warps 0-7 consumers (4m x 2n, 32x32 tiles), warps 8-15 producers.
// ---------------------------------------------------------------------------
template<int L1>
__global__ void __launch_bounds__(512, 1)
rec_layer(const float* __restrict__ Uw,
          const float* __restrict__ Z,
          float* __restrict__ Hbuf,
          unsigned* __restrict__ bar)
{
    constexpr int BM = 128, BN = 64, BK = 64, PAD = 68, KT = 16;
    constexpr int MT = 2, NT = 4;
    constexpr int SFL  = (BM + BN) * PAD;
    constexpr int ZOFF = 3 * SFL;
    constexpr int ZPAD = 68;
    const size_t BH  = (size_t)BATCH * HIDDEN;
    const size_t BG4 = (size_t)BATCH * G4;

    extern __shared__ float sm[];
    const uint32_t sbase = smem_to_u32(sm);

    const int tid  = threadIdx.x;
    const int wid  = tid >> 5;
    const int lane = tid & 31;
    const bool prod = (wid >= 8);
    const int ptid = tid - 256;
    const int m0   = blockIdx.y * BM;
    const int n0   = blockIdx.x * BN;
    const int r    = lane >> 2;
    const int cq   = lane & 3;
    const int l8   = lane & 7;
    const int sid  = lane >> 3;

    const int wm0  = (wid >> 1) * 32;
    const int wn0  = (wid & 1) * 32;

    uint32_t a_off[MT], b_off[2];
    #pragma unroll
    for (int mt = 0; mt < MT; mt++)
        a_off[mt] = (uint32_t)(((wm0 + mt * 16 + (sid & 1) * 8 + l8) * PAD
                                + (sid >> 1) * 4) * 4);
    #pragma unroll
    for (int p = 0; p < 2; p++)
        b_off[p] = (uint32_t)(((BM + wn0 + p * 16 + (sid >> 1) * 8 + l8) * PAD
                                + (sid & 1) * 4) * 4);

    float creg[MT * NT * 2] = {};

    #pragma unroll 1
    for (int t = 0; t < SEQ; t++) {
        const float* A    = Hbuf + (size_t)(L1 ? t : (t & 1)) * BH;
        float*       Hout = Hbuf + (size_t)(L1 ? (t + 1) : ((t + 1) & 1)) * BH;
        const float* Zt   = Z + (size_t)t * BG4;

        float acc[MT][NT][4] = {};

        auto load_stage = [&](int kt, bool with_z) {
            const int s3 = kt % 3;
            const uint32_t dst = sbase + (uint32_t)s3 * (SFL * 4);
            const float* Ag = A  + (size_t)m0 * HIDDEN + kt * BK;
            const float* Bg = Uw + (size_t)n0 * HIDDEN + kt * BK;
            #pragma unroll
            for (int i = 0; i < 8; i++) {
                int cid = ptid + i * 256;
                int row = cid >> 4, c = cid & 15;
                cp_async16(dst + (uint32_t)(row * PAD * 4) + c * 16,
                           Ag + (size_t)row * HIDDEN + c * 4);
            }
            #pragma unroll
            for (int i = 0; i < 4; i++) {
                int cid = ptid + i * 256;
                int row = cid >> 4, c = cid & 15;
                cp_async16(dst + (uint32_t)((BM + row) * PAD * 4) + c * 16,
                           Bg + (size_t)row * HIDDEN + c * 4);
            }
            if (with_z) {
                #pragma unroll
                for (int i = 0; i < 8; i++) {
                    int cid = ptid + i * 256;
                    int row = cid >> 4, c = cid & 15;
                    cp_async16(sbase + (uint32_t)((ZOFF + row * ZPAD) * 4) + c * 16,
                               Zt + (size_t)(m0 + row) * G4 + n0 + c * 4);
                }
            }
            asm volatile("cp.async.commit_group;\n");
        };

        if (prod) {
            load_stage(0, false);
            load_stage(1, true);
        }

        #pragma unroll 1
        for (int kt = 0; kt < KT; kt++) {
            if (prod) {
                if (kt < KT - 1) asm volatile("cp.async.wait_group 1;\n");
                else             asm volatile("cp.async.wait_group 0;\n");
            }
            __syncthreads();

            if (prod) {
                if (kt + 2 < KT) load_stage(kt + 2, false);
            } else {
                const uint32_t stg = sbase + (uint32_t)(kt % 3) * (SFL * 4);
                #pragma unroll
                for (int ks = 0; ks < 8; ks++) {
                    uint32_t af[MT][4], bf[NT][2];
                    #pragma unroll
                    for (int mt = 0; mt < MT; mt++)
                        LDSM_X4(af[mt][0], af[mt][1], af[mt][2], af[mt][3],
                                stg + a_off[mt] + ks * 32);
                    #pragma unroll
                    for (int p = 0; p < 2; p++) {
                        uint32_t q0, q1, q2, q3;
                        LDSM_X4(q0, q1, q2, q3, stg + b_off[p] + ks * 32);
                        bf[2 * p][0] = q0; bf[2 * p][1] = q1;
                        bf[2 * p + 1][0] = q2; bf[2 * p + 1][1] = q3;
                    }
                    #pragma unroll
                    for (int mt = 0; mt < MT; mt++)
                        #pragma unroll
                        for (int nt = 0; nt < NT; nt++)
                            mma_tf32_16n8k8(acc[mt][nt], af[mt], bf[nt]);
                }
            }
        }

        if (!prod) {
            #pragma unroll
            for (int mt = 0; mt < MT; mt++) {
                #pragma unroll
                for (int nt = 0; nt < NT; nt++) {
                    const int rl   = wm0 + mt * 16 + r;
                    const int cl   = wn0 + nt * 8 + cq * 2;
                    float v0 = acc[mt][nt][0], v1 = acc[mt][nt][1];
                    float v2 = acc[mt][nt][2], v3 = acc[mt][nt][3];
                    float2 z01 = *reinterpret_cast<const float2*>(sm + ZOFF + rl * ZPAD + cl);
                    float2 z23 = *reinterpret_cast<const float2*>(sm + ZOFF + (rl + 8) * ZPAD + cl);
                    v0 += z01.x; v1 += z01.y; v2 += z23.x; v3 += z23.y;
                    float p0 = __shfl_xor_sync(0xffffffffu, v0, 1);
                    float p1 = __shfl_xor_sync(0xffffffffu, v1, 1);
                    float p2 = __shfl_xor_sync(0xffffffffu, v2, 1);
                    float p3 = __shfl_xor_sync(0xffffffffu, v3, 1);
                    if ((lane & 1) == 0) {
                        const int row = m0 + rl;
                        const int j   = (n0 + cl) >> 2;
                        const int ci  = (mt * NT + nt) * 2;
                        float cn = sigf(v1) * creg[ci] + sigf(v0) * tanhf(p0);
                        creg[ci] = cn;
                        Hout[(size_t)row * HIDDEN + j] = to_tf32(sigf(p1) * tanhf(cn));
                        float cn2 = sigf(v3) * creg[ci + 1] + sigf(v2) * tanhf(p2);
                        creg[ci + 1] = cn2;
                        Hout[(size_t)(row + 8) * HIDDEN + j] = to_tf32(sigf(p3) * tanhf(cn2));
                    }
                }
            }
        }

        if (t < SEQ - 1) {
            __syncthreads();
            if (tid == 0) {
                __threadfence();
                atomicAdd(&bar[t], 1u);
                volatile unsigned* p = bar + t;
                while (*p < REC_CTAS) { }
                __threadfence();
            }
            __syncthreads();
        }
    }
}

// ---------------------------------------------------------------------------
// Weight transpose + gate interleave: out[4j+g, k] = in[k, g*H + j]
// ---------------------------------------------------------------------------
__global__ void reorder_w_all(const float* __restrict__ W1, const float* __restrict__ U1,
                              const float* __restrict__ W2, const float* __restrict__ U2,
                              float* __restrict__ W1r, float* __restrict__ U1T,
                              float* __restrict__ W2r, float* __restrict__ U2T)
{
    __shared__ float tile[32][33];
    const int z  = blockIdx.z;
    const int mi = z >> 2, g = z & 3;
    const int K  = (mi == 0) ? INPUT : HIDDEN;
    const int k0 = blockIdx.x * 32;
    if (k0 >= K) return;
    const int j0 = blockIdx.y * 32;
    const float* in  = (mi == 0) ? W1 : (mi == 1) ? U1 : (mi == 2) ? W2 : U2;
    float*       out = (mi == 0) ? W1r : (mi == 1) ? U1T : (mi == 2) ? W2r : U2T;
    const int tx = threadIdx.x, ty = threadIdx.y;
    tile[ty][tx] = in[(size_t)(k0 + ty) * G4 + g * HIDDEN + j0 + tx];
    __syncthreads();
    out[(size_t)(4 * (j0 + ty) + g) * K + k0 + tx] = to_tf32(tile[tx][ty]);
}

// ---------------------------------------------------------------------------
// Misc init: bias reorder + state zero + barrier zero (one launch)
// ---------------------------------------------------------------------------
__global__ void misc_init(const float* __restrict__ b1, const float* __restrict__ b2,
                          float* __restrict__ b1r, float* __restrict__ b2r,
                          float* __restrict__ H1_0, float* __restrict__ h2_0,
                          unsigned* __restrict__ bar1, unsigned* __restrict__ bar2)
{
    int flat = blockIdx.x * blockDim.x + threadIdx.x;
    if (flat < G4)           b1r[flat] = b1[(flat & 3) * HIDDEN + (flat >> 2)];
    else if (flat < 2 * G4) { int m = flat - G4; b2r[m] = b2[(m & 3) * HIDDEN + (m >> 2)]; }
    if (flat < BATCH * HIDDEN) { H1_0[flat] = 0.f; h2_0[flat] = 0.f; }
    if (flat < SEQ) { bar1[flat] = 0u; bar2[flat] = 0u; }
}

// ---------------------------------------------------------------------------
// Pack x: [B, S, I] -> [S*B, I]  (row m = t*B + b), tf32-rounded
// ---------------------------------------------------------------------------
__global__ void pack_x_kernel(const float4* __restrict__ x, float4* __restrict__ xp) {
    int n = blockIdx.x * blockDim.x + threadIdx.x;
    const int I4 = INPUT / 4;
    int k = n % I4;
    int rr = n / I4;
    int b = rr % BATCH;
    int t = rr / BATCH;
    float4 v = x[((size_t)b * SEQ + t) * I4 + k];
    v.x = to_tf32(v.x); v.y = to_tf32(v.y); v.z = to_tf32(v.z); v.w = to_tf32(v.w);
    xp[n] = v;
}

// ---------------------------------------------------------------------------
// Final projection (M=256, N=1000, K=1024) — scalar fp32 (exact)
// ---------------------------------------------------------------------------
__global__ void final_proj_kernel(const float* __restrict__ A,
                                  const float* __restrict__ B,
                                  const float* __restrict__ bias,
                                  float* __restrict__ C)
{
    constexpr int BM = 64, BN = 64, BK = 16, TM = 4, TN = 4, TX = 16;
    __shared__ float As[BK][BM];
    __shared__ float Bs[BK][BN];
    const int tid  = threadIdx.x;
    const int tx   = tid % TX;
    const int ty   = tid / TX;
    const int brow = blockIdx.y * BM;
    const int bcol = blockIdx.x * BN;
    float acc[TM][TN] = {};

    for (int kt = 0; kt < HIDDEN; kt += BK) {
        {
            int ar = tid / (BK / 4);
            int ak = (tid % (BK / 4)) * 4;
            float4 v = *reinterpret_cast<const float4*>(A + (size_t)(brow + ar) * HIDDEN + kt + ak);
            As[ak + 0][ar] = v.x; As[ak + 1][ar] = v.y; As[ak + 2][ar] = v.z; As[ak + 3][ar] = v.w;
        }
        {
            int bk = tid / (BN / 4);
            int bn = (tid % (BN / 4)) * 4;
            int col = bcol + bn;
            const float* src = B + (size_t)(kt + bk) * CLASSES + col;
            Bs[bk][bn + 0] = (col + 0 < CLASSES) ? src[0] : 0.f;
            Bs[bk][bn + 1] = (col + 1 < CLASSES) ? src[1] : 0.f;
            Bs[bk][bn + 2] = (col + 2 < CLASSES) ? src[2] : 0.f;
            Bs[bk][bn + 3] = (col + 3 < CLASSES) ? src[3] : 0.f;
        }
        __syncthreads();
        #pragma unroll
        for (int k = 0; k < BK; k++) {
            float ra[TM], rb[TN];
            #pragma unroll
            for (int i = 0; i < TM; i++) ra[i] = As[k][ty * TM + i];
            #pragma unroll
            for (int j = 0; j < TN; j++) rb[j] = Bs[k][tx * TN + j];
            #pragma unroll
            for (int i = 0; i < TM; i++)
                #pragma unroll
                for (int j = 0; j < TN; j++)
                    acc[i][j] += ra[i] * rb[j];
        }
        __syncthreads();
    }
    #pragma unroll
    for (int i = 0; i < TM; i++) {
        int rr = brow + ty * TM + i;
        #pragma unroll
        for (int j = 0; j < TN; j++) {
            int col = bcol + tx * TN + j;
            if (col < CLASSES)
                C[(size_t)rr * CLASSES + col] = acc[i][j] + bias[col];
        }
    }
}

// ---------------------------------------------------------------------------
// Launch (8 nodes; launch #4 = mma_gemm_bias<16> (GEMM1) for ncu capture)
// ---------------------------------------------------------------------------
extern "C" void kernel_launch(void* const* d_in, const int* in_sizes, int n_in,
                              void* d_out, int out_size)
{
    const float* x  = (const float*)d_in[0];
    const float* W1 = (const float*)d_in[1];
    const float* U1 = (const float*)d_in[2];
    const float* b1 = (const float*)d_in[3];
    const float* W2 = (const float*)d_in[4];
    const float* U2 = (const float*)d_in[5];
    const float* b2 = (const float*)d_in[6];
    const float* Wo = (const float*)d_in[7];
    const float* bo = (const float*)d_in[8];
    float* out = (float*)d_out;

    float *X, *Z, *H1, *h2, *W1r, *U1T, *W2r, *U2T, *b1r, *b2r;
    unsigned *bar1, *bar2;
    cudaGetSymbolAddress((void**)&X,   g_X);
    cudaGetSymbolAddress((void**)&Z,   g_Z);
    cudaGetSymbolAddress((void**)&H1,  g_H1);
    cudaGetSymbolAddress((void**)&h2,  g_h2);
    cudaGetSymbolAddress((void**)&W1r, g_W1r);
    cudaGetSymbolAddress((void**)&U1T, g_U1T);
    cudaGetSymbolAddress((void**)&W2r, g_W2r);
    cudaGetSymbolAddress((void**)&U2T, g_U2T);
    cudaGetSymbolAddress((void**)&b1r, g_b1r);
    cudaGetSymbolAddress((void**)&b2r, g_b2r);
    cudaGetSymbolAddress((void**)&bar1, g_bar1);
    cudaGetSymbolAddress((void**)&bar2, g_bar2);

    const int SMEM_BIG = 3 * (128 + 128) * 36 * 4;                    // 110592
    const int SMEM_REC = (3 * (128 + 64) * 68 + 128 * 68) * 4;        // 191488
    cudaFuncSetAttribute(mma_gemm_bias<16>, cudaFuncAttributeMaxDynamicSharedMemorySize, SMEM_BIG);
    cudaFuncSetAttribute(mma_gemm_bias<32>, cudaFuncAttributeMaxDynamicSharedMemorySize, SMEM_BIG);
    cudaFuncSetAttribute(rec_layer<1>, cudaFuncAttributeMaxDynamicSharedMemorySize, SMEM_REC);
    cudaFuncSetAttribute(rec_layer<0>, cudaFuncAttributeMaxDynamicSharedMemorySize, SMEM_REC);

    const size_t BH = (size_t)BATCH * HIDDEN;

    // 1) pack X
    pack_x_kernel<<<SB * INPUT / 4 / 256, 256>>>((const float4*)x, (float4*)X);
    // 2) reorder weights
    reorder_w_all<<<dim3(32, 32, 16), dim3(32, 32)>>>(W1, U1, W2, U2, W1r, U1T, W2r, U2T);
    // 3) biases + state + barrier init
    misc_init<<<(BATCH * HIDDEN) / 256, 256>>>(b1, b2, b1r, b2r, H1, h2, bar1, bar2);
    // 4) Z = X @ W1r^T + b1r  (K=512, KT=16)   <-- ncu capture slot
    mma_gemm_bias<16><<<dim3(G4 / 128, SB / 128), 256, SMEM_BIG>>>(X, INPUT, W1r, b1r, Z);
    // 5) layer-1 recurrence
    rec_layer<1><<<dim3(64, 2), 512, SMEM_REC>>>(U1T, Z, H1, bar1);
    // 6) Z = H1[1..64] @ W2r^T + b2r  (K=1024, KT=32)
    mma_gemm_bias<32><<<dim3(G4 / 128, SB / 128), 256, SMEM_BIG>>>(H1 + BH, HIDDEN, W2r, b2r, Z);
    // 7) layer-2 recurrence
    rec_layer<0><<<dim3(64, 2), 512, SMEM_REC>>>(U2T, Z, h2, bar2);
    // 8) out = h2[0] @ Wo + bo
    final_proj_kernel<<<dim3((CLASSES + 63) / 64, BATCH / 64), 256>>>(h2, Wo, bo, out);
}

// round 14
// speedup vs baseline: 1.1798x; 1.0914x over previous
#include <cuda_runtime.h>
#include <cstdint>
#include <cstddef>

#define BATCH   256
#define SEQ     64
#define INPUT   512
#define HIDDEN  1024
#define CLASSES 1000
#define SB      (SEQ * BATCH)   // 16384
#define G4      (4 * HIDDEN)    // 4096
#define REC_CTAS 128u

// ---------------------------------------------------------------------------
// Scratch (device globals — no allocations allowed)
// ---------------------------------------------------------------------------
__device__ float g_X  [SB * INPUT];
__device__ float g_Z  [(size_t)SB * G4];
__device__ float g_H1 [(SEQ + 1) * BATCH * HIDDEN];
__device__ float g_h2 [2 * BATCH * HIDDEN];
__device__ float g_W1r[(size_t)G4 * INPUT];
__device__ float g_U1T[(size_t)G4 * HIDDEN];
__device__ float g_W2r[(size_t)G4 * HIDDEN];
__device__ float g_U2T[(size_t)G4 * HIDDEN];
__device__ float g_b1r[G4];
__device__ float g_b2r[G4];
__device__ unsigned g_bar1[SEQ];
__device__ unsigned g_bar2[SEQ];

// ---------------------------------------------------------------------------
// Helpers
// ---------------------------------------------------------------------------
__device__ __forceinline__ uint32_t smem_to_u32(const void* p) {
    uint32_t a;
    asm("{ .reg .u64 t; cvta.to.shared.u64 t, %1; cvt.u32.u64 %0, t; }"
        : "=r"(a) : "l"(p));
    return a;
}

__device__ __forceinline__ float to_tf32(float x) {
    uint32_t r;
    asm("cvt.rna.tf32.f32 %0, %1;" : "=r"(r) : "f"(x));
    return __uint_as_float(r);
}

__device__ __forceinline__ void cp_async16(uint32_t smem_dst, const void* gmem_src) {
    asm volatile("cp.async.cg.shared.global [%0], [%1], 16;\n" :: "r"(smem_dst), "l"(gmem_src));
}

__device__ __forceinline__ void mma_tf32_16n8k8(float* d, const uint32_t* a, const uint32_t* b) {
    asm volatile(
        "mma.sync.aligned.m16n8k8.row.col.f32.tf32.tf32.f32 "
        "{%0,%1,%2,%3}, {%4,%5,%6,%7}, {%8,%9}, {%0,%1,%2,%3};"
        : "+f"(d[0]), "+f"(d[1]), "+f"(d[2]), "+f"(d[3])
        : "r"(a[0]), "r"(a[1]), "r"(a[2]), "r"(a[3]), "r"(b[0]), "r"(b[1]));
}

#define LDSM_X4(r0, r1, r2, r3, addr) \
    asm volatile("ldmatrix.sync.aligned.m8n8.x4.shared.b16 {%0,%1,%2,%3}, [%4];" \
        : "=r"(r0), "=r"(r1), "=r"(r2), "=r"(r3) : "r"(addr))

__device__ __forceinline__ float sigf(float x) { return 1.f / (1.f + expf(-x)); }

// ---------------------------------------------------------------------------
// Big GEMM v3 (UNCHANGED from round 13 — protected win):
// 256 threads / 8 warps (2m x 4n, 64x32 tiles), BK=32, 3-stage ring,
// one sync per k-tile, 2 CTAs/SM.
// ---------------------------------------------------------------------------
template<int KT>
__global__ void __launch_bounds__(256, 2)
mma_gemm_bias(const float* __restrict__ A, int lda,
              const float* __restrict__ Bt,
              const float* __restrict__ bias,
              float* __restrict__ C)
{
    constexpr int BM = 128, BN = 128, BK = 32, PAD = 36;
    constexpr int MT = 4, NT = 4;
    constexpr int SFL = (BM + BN) * PAD;

    extern __shared__ float sm[];
    const uint32_t sbase = smem_to_u32(sm);

    const int tid  = threadIdx.x;
    const int wid  = tid >> 5;
    const int lane = tid & 31;
    const int wm0  = (wid >> 2) * 64;
    const int wn0  = (wid & 3) * 32;
    const int m0   = blockIdx.y * BM;
    const int n0   = blockIdx.x * BN;
    const int K    = KT * BK;
    const int r    = lane >> 2;
    const int cq   = lane & 3;
    const int l8   = lane & 7;
    const int sid  = lane >> 3;

    uint32_t a_off[MT], b_off[2];
    #pragma unroll
    for (int mt = 0; mt < MT; mt++)
        a_off[mt] = (uint32_t)(((wm0 + mt * 16 + (sid & 1) * 8 + l8) * PAD
                                + (sid >> 1) * 4) * 4);
    #pragma unroll
    for (int p = 0; p < 2; p++)
        b_off[p] = (uint32_t)(((BM + wn0 + p * 16 + (sid >> 1) * 8 + l8) * PAD
                                + (sid & 1) * 4) * 4);

    float acc[MT][NT][4] = {};

    auto load_stage = [&](int kt) {
        const uint32_t dst = sbase + (uint32_t)(kt % 3) * (SFL * 4);
        const float* Ag = A  + (size_t)m0 * lda + kt * BK;
        const float* Bg = Bt + (size_t)n0 * K   + kt * BK;
        #pragma unroll
        for (int i = 0; i < 4; i++) {
            int cid = tid + i * 256;
            int row = cid >> 3, c = cid & 7;
            cp_async16(dst + (uint32_t)(row * PAD * 4) + c * 16,
                       Ag + (size_t)row * lda + c * 4);
        }
        #pragma unroll
        for (int i = 0; i < 4; i++) {
            int cid = tid + i * 256;
            int row = cid >> 3, c = cid & 7;
            cp_async16(dst + (uint32_t)((BM + row) * PAD * 4) + c * 16,
                       Bg + (size_t)row * K + c * 4);
        }
        asm volatile("cp.async.commit_group;\n");
    };

    load_stage(0);
    if (KT > 1) load_stage(1);

    #pragma unroll 1
    for (int kt = 0; kt < KT; kt++) {
        if (kt < KT - 1) asm volatile("cp.async.wait_group 1;\n");
        else             asm volatile("cp.async.wait_group 0;\n");
        __syncthreads();

        if (kt + 2 < KT) load_stage(kt + 2);

        const uint32_t stg = sbase + (uint32_t)(kt % 3) * (SFL * 4);

        #pragma unroll
        for (int ks = 0; ks < 4; ks++) {
            uint32_t af[MT][4], bf[NT][2];
            #pragma unroll
            for (int mt = 0; mt < MT; mt++)
                LDSM_X4(af[mt][0], af[mt][1], af[mt][2], af[mt][3],
                        stg + a_off[mt] + ks * 32);
            #pragma unroll
            for (int p = 0; p < 2; p++) {
                uint32_t q0, q1, q2, q3;
                LDSM_X4(q0, q1, q2, q3, stg + b_off[p] + ks * 32);
                bf[2 * p][0] = q0; bf[2 * p][1] = q1;
                bf[2 * p + 1][0] = q2; bf[2 * p + 1][1] = q3;
            }
            #pragma unroll
            for (int mt = 0; mt < MT; mt++)
                #pragma unroll
                for (int nt = 0; nt < NT; nt++)
                    mma_tf32_16n8k8(acc[mt][nt], af[mt], bf[nt]);
        }
    }

    #pragma unroll
    for (int mt = 0; mt < MT; mt++) {
        #pragma unroll
        for (int nt = 0; nt < NT; nt++) {
            const int row  = m0 + wm0 + mt * 16 + r;
            const int colb = n0 + wn0 + nt * 8 + cq * 2;
            float2 bv = *reinterpret_cast<const float2*>(bias + colb);
            float2 o01 = { acc[mt][nt][0] + bv.x, acc[mt][nt][1] + bv.y };
            float2 o23 = { acc[mt][nt][2] + bv.x, acc[mt][nt][3] + bv.y };
            *reinterpret_cast<float2*>(C + (size_t)row * G4 + colb)       = o01;
            *reinterpret_cast<float2*>(C + (size_t)(row + 8) * G4 + colb) = o23;
        }
    }
}

// ---------------------------------------------------------------------------
// Persistent recurrence v7: 384 threads / 12 warps.
// Warps 0-7 = consumers (4m x 2n, warp tile 32x32, MT=2/NT=4) with
// FRAGMENT DOUBLE-BUFFERING (reg cap 170 at 384 thr allows it).
// Warps 8-11 = producers (128 threads, all cp.async).
// BM=128, BN=64, BK=64, KT=16, 3 stages, Z prefetch, reg c-state, grid barrier.
// ---------------------------------------------------------------------------
template<int L1>
__global__ void __launch_bounds__(384, 1)
rec_layer(const float* __restrict__ Uw,
          const float* __restrict__ Z,
          float* __restrict__ Hbuf,
          unsigned* __restrict__ bar)
{
    constexpr int BM = 128, BN = 64, BK = 64, PAD = 68, KT = 16;
    constexpr int MT = 2, NT = 4;
    constexpr int SFL  = (BM + BN) * PAD;
    constexpr int ZOFF = 3 * SFL;
    constexpr int ZPAD = 68;
    const size_t BH  = (size_t)BATCH * HIDDEN;
    const size_t BG4 = (size_t)BATCH * G4;

    extern __shared__ float sm[];
    const uint32_t sbase = smem_to_u32(sm);

    const int tid  = threadIdx.x;
    const int wid  = tid >> 5;                 // 0..11
    const int lane = tid & 31;
    const bool prod = (wid >= 8);
    const int ptid = tid - 256;                // producer-local 0..127
    const int m0   = blockIdx.y * BM;
    const int n0   = blockIdx.x * BN;
    const int r    = lane >> 2;
    const int cq   = lane & 3;
    const int l8   = lane & 7;
    const int sid  = lane >> 3;

    // consumers: 8 warps, 4m x 2n, warp tile 32x32
    const int wm0  = (wid >> 1) * 32;
    const int wn0  = (wid & 1) * 32;

    uint32_t a_off[MT], b_off[2];
    #pragma unroll
    for (int mt = 0; mt < MT; mt++)
        a_off[mt] = (uint32_t)(((wm0 + mt * 16 + (sid & 1) * 8 + l8) * PAD
                                + (sid >> 1) * 4) * 4);
    #pragma unroll
    for (int p = 0; p < 2; p++)
        b_off[p] = (uint32_t)(((BM + wn0 + p * 16 + (sid >> 1) * 8 + l8) * PAD
                                + (sid & 1) * 4) * 4);

    float creg[MT * NT * 2] = {};

    #pragma unroll 1
    for (int t = 0; t < SEQ; t++) {
        const float* A    = Hbuf + (size_t)(L1 ? t : (t & 1)) * BH;
        float*       Hout = Hbuf + (size_t)(L1 ? (t + 1) : ((t + 1) & 1)) * BH;
        const float* Zt   = Z + (size_t)t * BG4;

        float acc[MT][NT][4] = {};

        // producer stage loader (128 producer threads)
        auto load_stage = [&](int kt, bool with_z) {
            const int s3 = kt % 3;
            const uint32_t dst = sbase + (uint32_t)s3 * (SFL * 4);
            const float* Ag = A  + (size_t)m0 * HIDDEN + kt * BK;
            const float* Bg = Uw + (size_t)n0 * HIDDEN + kt * BK;
            // A: 128 rows x 16 chunks = 2048 chunks / 128 thr = 16 each
            #pragma unroll
            for (int i = 0; i < 16; i++) {
                int cid = ptid + i * 128;
                int row = cid >> 4, c = cid & 15;
                cp_async16(dst + (uint32_t)(row * PAD * 4) + c * 16,
                           Ag + (size_t)row * HIDDEN + c * 4);
            }
            // B: 64 rows x 16 chunks = 1024 chunks / 128 = 8 each
            #pragma unroll
            for (int i = 0; i < 8; i++) {
                int cid = ptid + i * 128;
                int row = cid >> 4, c = cid & 15;
                cp_async16(dst + (uint32_t)((BM + row) * PAD * 4) + c * 16,
                           Bg + (size_t)row * HIDDEN + c * 4);
            }
            if (with_z) {
                // Z tile: 128 rows x 16 chunks = 2048 chunks
                #pragma unroll
                for (int i = 0; i < 16; i++) {
                    int cid = ptid + i * 128;
                    int row = cid >> 4, c = cid & 15;
                    cp_async16(sbase + (uint32_t)((ZOFF + row * ZPAD) * 4) + c * 16,
                               Zt + (size_t)(m0 + row) * G4 + n0 + c * 4);
                }
            }
            asm volatile("cp.async.commit_group;\n");
        };

        if (prod) {
            load_stage(0, false);
            load_stage(1, true);
        }

        #pragma unroll 1
        for (int kt = 0; kt < KT; kt++) {
            if (prod) {
                if (kt < KT - 1) asm volatile("cp.async.wait_group 1;\n");
                else             asm volatile("cp.async.wait_group 0;\n");
            }
            __syncthreads();          // stage kt ready; stage (kt+2)%3 free

            if (prod) {
                if (kt + 2 < KT) load_stage(kt + 2, false);
            } else {
                const uint32_t stg = sbase + (uint32_t)(kt % 3) * (SFL * 4);

                // fragment double-buffer across the 8 k-slices
                uint32_t af[2][MT][4], bf[2][NT][2];
                auto load_frags = [&](int ks, int b) {
                    #pragma unroll
                    for (int mt = 0; mt < MT; mt++)
                        LDSM_X4(af[b][mt][0], af[b][mt][1], af[b][mt][2], af[b][mt][3],
                                stg + a_off[mt] + ks * 32);
                    #pragma unroll
                    for (int p = 0; p < 2; p++) {
                        uint32_t q0, q1, q2, q3;
                        LDSM_X4(q0, q1, q2, q3, stg + b_off[p] + ks * 32);
                        bf[b][2 * p][0] = q0; bf[b][2 * p][1] = q1;
                        bf[b][2 * p + 1][0] = q2; bf[b][2 * p + 1][1] = q3;
                    }
                };

                load_frags(0, 0);
                #pragma unroll
                for (int ks = 0; ks < 8; ks++) {
                    const int cur = ks & 1;
                    if (ks < 7) load_frags(ks + 1, cur ^ 1);
                    #pragma unroll
                    for (int mt = 0; mt < MT; mt++)
                        #pragma unroll
                        for (int nt = 0; nt < NT; nt++)
                            mma_tf32_16n8k8(acc[mt][nt], af[cur][mt], bf[cur][nt]);
                }
            }
        }

        // ---- fused LSTM cell epilogue (consumers; Z from smem) ----
        if (!prod) {
            #pragma unroll
            for (int mt = 0; mt < MT; mt++) {
                #pragma unroll
                for (int nt = 0; nt < NT; nt++) {
                    const int rl   = wm0 + mt * 16 + r;
                    const int cl   = wn0 + nt * 8 + cq * 2;
                    float v0 = acc[mt][nt][0], v1 = acc[mt][nt][1];
                    float v2 = acc[mt][nt][2], v3 = acc[mt][nt][3];
                    float2 z01 = *reinterpret_cast<const float2*>(sm + ZOFF + rl * ZPAD + cl);
                    float2 z23 = *reinterpret_cast<const float2*>(sm + ZOFF + (rl + 8) * ZPAD + cl);
                    v0 += z01.x; v1 += z01.y; v2 += z23.x; v3 += z23.y;
                    float p0 = __shfl_xor_sync(0xffffffffu, v0, 1);
                    float p1 = __shfl_xor_sync(0xffffffffu, v1, 1);
                    float p2 = __shfl_xor_sync(0xffffffffu, v2, 1);
                    float p3 = __shfl_xor_sync(0xffffffffu, v3, 1);
                    if ((lane & 1) == 0) {
                        const int row = m0 + rl;
                        const int j   = (n0 + cl) >> 2;
                        const int ci  = (mt * NT + nt) * 2;
                        float cn = sigf(v1) * creg[ci] + sigf(v0) * tanhf(p0);
                        creg[ci] = cn;
                        Hout[(size_t)row * HIDDEN + j] = to_tf32(sigf(p1) * tanhf(cn));
                        float cn2 = sigf(v3) * creg[ci + 1] + sigf(v2) * tanhf(p2);
                        creg[ci + 1] = cn2;
                        Hout[(size_t)(row + 8) * HIDDEN + j] = to_tf32(sigf(p3) * tanhf(cn2));
                    }
                }
            }
        }

        // ---- grid barrier between steps ----
        if (t < SEQ - 1) {
            __syncthreads();
            if (tid == 0) {
                __threadfence();
                atomicAdd(&bar[t], 1u);
                volatile unsigned* p = bar + t;
                while (*p < REC_CTAS) { }
                __threadfence();
            }
            __syncthreads();
        }
    }
}

// ---------------------------------------------------------------------------
// Merged prologue: weight transpose+interleave (z<16), bias reorder + state
// zero + barrier zero (z==16).
// ---------------------------------------------------------------------------
__global__ void reorder_all(const float* __restrict__ W1, const float* __restrict__ U1,
                            const float* __restrict__ W2, const float* __restrict__ U2,
                            const float* __restrict__ b1, const float* __restrict__ b2,
                            float* __restrict__ W1r, float* __restrict__ U1T,
                            float* __restrict__ W2r, float* __restrict__ U2T,
                            float* __restrict__ b1r, float* __restrict__ b2r,
                            float* __restrict__ H1_0, float* __restrict__ h2_0,
                            unsigned* __restrict__ bar1, unsigned* __restrict__ bar2)
{
    const int z = blockIdx.z;
    if (z == 16) {
        int flat = (blockIdx.x * 32 + blockIdx.y) * 1024 + threadIdx.y * 32 + threadIdx.x;
        if (flat < G4)           b1r[flat] = b1[(flat & 3) * HIDDEN + (flat >> 2)];
        else if (flat < 2 * G4) { int m = flat - G4; b2r[m] = b2[(m & 3) * HIDDEN + (m >> 2)]; }
        if (flat < BATCH * HIDDEN) { H1_0[flat] = 0.f; h2_0[flat] = 0.f; }
        if (flat < SEQ) { bar1[flat] = 0u; bar2[flat] = 0u; }
        return;
    }
    __shared__ float tile[32][33];
    const int mi = z >> 2, g = z & 3;
    const int K  = (mi == 0) ? INPUT : HIDDEN;
    const int k0 = blockIdx.x * 32;
    if (k0 >= K) return;
    const int j0 = blockIdx.y * 32;
    const float* in  = (mi == 0) ? W1 : (mi == 1) ? U1 : (mi == 2) ? W2 : U2;
    float*       out = (mi == 0) ? W1r : (mi == 1) ? U1T : (mi == 2) ? W2r : U2T;
    const int tx = threadIdx.x, ty = threadIdx.y;
    tile[ty][tx] = in[(size_t)(k0 + ty) * G4 + g * HIDDEN + j0 + tx];
    __syncthreads();
    out[(size_t)(4 * (j0 + ty) + g) * K + k0 + tx] = to_tf32(tile[tx][ty]);
}

// ---------------------------------------------------------------------------
// Pack x: [B, S, I] -> [S*B, I]  (row m = t*B + b), tf32-rounded
// ---------------------------------------------------------------------------
__global__ void pack_x_kernel(const float4* __restrict__ x, float4* __restrict__ xp) {
    int n = blockIdx.x * blockDim.x + threadIdx.x;
    const int I4 = INPUT / 4;
    int k = n % I4;
    int rr = n / I4;
    int b = rr % BATCH;
    int t = rr / BATCH;
    float4 v = x[((size_t)b * SEQ + t) * I4 + k];
    v.x = to_tf32(v.x); v.y = to_tf32(v.y); v.z = to_tf32(v.z); v.w = to_tf32(v.w);
    xp[n] = v;
}

// ---------------------------------------------------------------------------
// Final projection (M=256, N=1000, K=1024) — scalar fp32 (exact)
// ---------------------------------------------------------------------------
__global__ void final_proj_kernel(const float* __restrict__ A,
                                  const float* __restrict__ B,
                                  const float* __restrict__ bias,
                                  float* __restrict__ C)
{
    constexpr int BM = 64, BN = 64, BK = 16, TM = 4, TN = 4, TX = 16;
    __shared__ float As[BK][BM];
    __shared__ float Bs[BK][BN];
    const int tid  = threadIdx.x;
    const int tx   = tid % TX;
    const int ty   = tid / TX;
    const int brow = blockIdx.y * BM;
    const int bcol = blockIdx.x * BN;
    float acc[TM][TN] = {};

    for (int kt = 0; kt < HIDDEN; kt += BK) {
        {
            int ar = tid / (BK / 4);
            int ak = (tid % (BK / 4)) * 4;
            float4 v = *reinterpret_cast<const float4*>(A + (size_t)(brow + ar) * HIDDEN + kt + ak);
            As[ak + 0][ar] = v.x; As[ak + 1][ar] = v.y; As[ak + 2][ar] = v.z; As[ak + 3][ar] = v.w;
        }
        {
            int bk = tid / (BN / 4);
            int bn = (tid % (BN / 4)) * 4;
            int col = bcol + bn;
            const float* src = B + (size_t)(kt + bk) * CLASSES + col;
            Bs[bk][bn + 0] = (col + 0 < CLASSES) ? src[0] : 0.f;
            Bs[bk][bn + 1] = (col + 1 < CLASSES) ? src[1] : 0.f;
            Bs[bk][bn + 2] = (col + 2 < CLASSES) ? src[2] : 0.f;
            Bs[bk][bn + 3] = (col + 3 < CLASSES) ? src[3] : 0.f;
        }
        __syncthreads();
        #pragma unroll
        for (int k = 0; k < BK; k++) {
            float ra[TM], rb[TN];
            #pragma unroll
            for (int i = 0; i < TM; i++) ra[i] = As[k][ty * TM + i];
            #pragma unroll
            for (int j = 0; j < TN; j++) rb[j] = Bs[k][tx * TN + j];
            #pragma unroll
            for (int i = 0; i < TM; i++)
                #pragma unroll
                for (int j = 0; j < TN; j++)
                    acc[i][j] += ra[i] * rb[j];
        }
        __syncthreads();
    }
    #pragma unroll
    for (int i = 0; i < TM; i++) {
        int rr = brow + ty * TM + i;
        #pragma unroll
        for (int j = 0; j < TN; j++) {
            int col = bcol + tx * TN + j;
            if (col < CLASSES)
                C[(size_t)rr * CLASSES + col] = acc[i][j] + bias[col];
        }
    }
}

// ---------------------------------------------------------------------------
// Launch (7 nodes; launch #4 = rec_layer<1> v7 for ncu capture)
// ---------------------------------------------------------------------------
extern "C" void kernel_launch(void* const* d_in, const int* in_sizes, int n_in,
                              void* d_out, int out_size)
{
    const float* x  = (const float*)d_in[0];
    const float* W1 = (const float*)d_in[1];
    const float* U1 = (const float*)d_in[2];
    const float* b1 = (const float*)d_in[3];
    const float* W2 = (const float*)d_in[4];
    const float* U2 = (const float*)d_in[5];
    const float* b2 = (const float*)d_in[6];
    const float* Wo = (const float*)d_in[7];
    const float* bo = (const float*)d_in[8];
    float* out = (float*)d_out;

    float *X, *Z, *H1, *h2, *W1r, *U1T, *W2r, *U2T, *b1r, *b2r;
    unsigned *bar1, *bar2;
    cudaGetSymbolAddress((void**)&X,   g_X);
    cudaGetSymbolAddress((void**)&Z,   g_Z);
    cudaGetSymbolAddress((void**)&H1,  g_H1);
    cudaGetSymbolAddress((void**)&h2,  g_h2);
    cudaGetSymbolAddress((void**)&W1r, g_W1r);
    cudaGetSymbolAddress((void**)&U1T, g_U1T);
    cudaGetSymbolAddress((void**)&W2r, g_W2r);
    cudaGetSymbolAddress((void**)&U2T, g_U2T);
    cudaGetSymbolAddress((void**)&b1r, g_b1r);
    cudaGetSymbolAddress((void**)&b2r, g_b2r);
    cudaGetSymbolAddress((void**)&bar1, g_bar1);
    cudaGetSymbolAddress((void**)&bar2, g_bar2);

    const int SMEM_BIG = 3 * (128 + 128) * 36 * 4;                    // 110592
    const int SMEM_REC = (3 * (128 + 64) * 68 + 128 * 68) * 4;        // 191488
    cudaFuncSetAttribute(mma_gemm_bias<16>, cudaFuncAttributeMaxDynamicSharedMemorySize, SMEM_BIG);
    cudaFuncSetAttribute(mma_gemm_bias<32>, cudaFuncAttributeMaxDynamicSharedMemorySize, SMEM_BIG);
    cudaFuncSetAttribute(rec_layer<1>, cudaFuncAttributeMaxDynamicSharedMemorySize, SMEM_REC);
    cudaFuncSetAttribute(rec_layer<0>, cudaFuncAttributeMaxDynamicSharedMemorySize, SMEM_REC);

    const size_t BH = (size_t)BATCH * HIDDEN;

    // 1) reorder weights + biases + state/barrier init (merged)
    reorder_all<<<dim3(32, 32, 17), dim3(32, 32)>>>(W1, U1, W2, U2, b1, b2,
                                                    W1r, U1T, W2r, U2T, b1r, b2r,
                                                    H1, h2, bar1, bar2);
    // 2) pack X
    pack_x_kernel<<<SB * INPUT / 4 / 256, 256>>>((const float4*)x, (float4*)X);
    // 3) Z = X @ W1r^T + b1r  (K=512, KT=16)
    mma_gemm_bias<16><<<dim3(G4 / 128, SB / 128), 256, SMEM_BIG>>>(X, INPUT, W1r, b1r, Z);
    // 4) layer-1 recurrence v7 (384 thr)   <-- ncu capture slot
    rec_layer<1><<<dim3(64, 2), 384, SMEM_REC>>>(U1T, Z, H1, bar1);
    // 5) Z = H1[1..64] @ W2r^T + b2r  (K=1024, KT=32)
    mma_gemm_bias<32><<<dim3(G4 / 128, SB / 128), 256, SMEM_BIG>>>(H1 + BH, HIDDEN, W2r, b2r, Z);
    // 6) layer-2 recurrence v7
    rec_layer<0><<<dim3(64, 2), 384, SMEM_REC>>>(U2T, Z, h2, bar2);
    // 7) out = h2[0] @ Wo + bo
    final_proj_kernel<<<dim3((CLASSES + 63) / 64, BATCH / 64), 256>>>(h2, Wo, bo, out);
}

// round 16
// speedup vs baseline: 1.1950x; 1.0128x over previous
#include <cuda_runtime.h>
#include <cstdint>
#include <cstddef>

#define BATCH   256
#define SEQ     64
#define INPUT   512
#define HIDDEN  1024
#define CLASSES 1000
#define SB      (SEQ * BATCH)   // 16384
#define G4      (4 * HIDDEN)    // 4096
#define REC_CTAS 128u

// ---------------------------------------------------------------------------
// Scratch (device globals — no allocations allowed)
// ---------------------------------------------------------------------------
__device__ float g_X  [SB * INPUT];
__device__ float g_Z  [(size_t)SB * G4];
__device__ float g_H1 [(SEQ + 1) * BATCH * HIDDEN];
__device__ float g_h2 [2 * BATCH * HIDDEN];
__device__ float g_W1r[(size_t)G4 * INPUT];
__device__ float g_U1T[(size_t)G4 * HIDDEN];
__device__ float g_W2r[(size_t)G4 * HIDDEN];
__device__ float g_U2T[(size_t)G4 * HIDDEN];
__device__ float g_b1r[G4];
__device__ float g_b2r[G4];
__device__ unsigned g_bar1[SEQ];
__device__ unsigned g_bar2[SEQ];

// ---------------------------------------------------------------------------
// Helpers
// ---------------------------------------------------------------------------
__device__ __forceinline__ uint32_t smem_to_u32(const void* p) {
    uint32_t a;
    asm("{ .reg .u64 t; cvta.to.shared.u64 t, %1; cvt.u32.u64 %0, t; }"
        : "=r"(a) : "l"(p));
    return a;
}

__device__ __forceinline__ float to_tf32(float x) {
    uint32_t r;
    asm("cvt.rna.tf32.f32 %0, %1;" : "=r"(r) : "f"(x));
    return __uint_as_float(r);
}

__device__ __forceinline__ void cp_async16(uint32_t smem_dst, const void* gmem_src) {
    asm volatile("cp.async.cg.shared.global [%0], [%1], 16;\n" :: "r"(smem_dst), "l"(gmem_src));
}

__device__ __forceinline__ void mma_tf32_16n8k8(float* d, const uint32_t* a, const uint32_t* b) {
    asm volatile(
        "mma.sync.aligned.m16n8k8.row.col.f32.tf32.tf32.f32 "
        "{%0,%1,%2,%3}, {%4,%5,%6,%7}, {%8,%9}, {%0,%1,%2,%3};"
        : "+f"(d[0]), "+f"(d[1]), "+f"(d[2]), "+f"(d[3])
        : "r"(a[0]), "r"(a[1]), "r"(a[2]), "r"(a[3]), "r"(b[0]), "r"(b[1]));
}

#define LDSM_X4(r0, r1, r2, r3, addr) \
    asm volatile("ldmatrix.sync.aligned.m8n8.x4.shared.b16 {%0,%1,%2,%3}, [%4];" \
        : "=r"(r0), "=r"(r1), "=r"(r2), "=r"(r3) : "r"(addr))

#define MBARRIER_INIT(addr, cnt) \
    asm volatile("mbarrier.init.shared.b64 [%0], %1;" :: "r"((uint32_t)(addr)), "r"((uint32_t)(cnt)) : "memory")

#define MBARRIER_ARRIVE(addr) \
    asm volatile("mbarrier.arrive.shared.b64 _, [%0];" :: "r"((uint32_t)(addr)) : "memory")

// .noinc: completion-arrive counts against the INITIALIZED expected count
// (the default form increments-then-decrements = net zero = deadlock).
#define CPASYNC_MBAR_ARRIVE_NOINC(addr) \
    asm volatile("cp.async.mbarrier.arrive.noinc.shared.b64 [%0];" :: "r"((uint32_t)(addr)) : "memory")

#define MBARRIER_WAIT_PARITY(mbar_smem_addr, phase_parity) do { \
    uint32_t _mbar = (uint32_t)(mbar_smem_addr); \
    uint32_t _parity = (uint32_t)(phase_parity); \
    uint32_t _done; \
    asm volatile( \
        "{\n\t.reg .pred p;\n\t" \
        "mbarrier.try_wait.parity.acquire.cta.shared::cta.b64 p, [%1], %2;\n\t" \
        "selp.b32 %0, 1, 0, p;\n\t}" \
        : "=r"(_done) : "r"(_mbar), "r"(_parity) : "memory"); \
    if (!_done) { \
        asm volatile( \
            "{\n\t.reg .pred P1;\n\t" \
            "WAIT_LOOP_%=:\n\t" \
            "mbarrier.try_wait.parity.acquire.cta.shared::cta.b64 P1, [%0], %1, 0x989680;\n\t" \
            "@P1 bra.uni WAIT_DONE_%=;\n\t" \
            "bra.uni WAIT_LOOP_%=;\n\t" \
            "WAIT_DONE_%=:\n\t}" \
            :: "r"(_mbar), "r"(_parity) : "memory"); \
    } \
} while(0)

__device__ __forceinline__ float sigf(float x) { return 1.f / (1.f + expf(-x)); }

// ---------------------------------------------------------------------------
// Big GEMM v3 (UNCHANGED — protected win): 256 thr / 8 warps (2m x 4n, 64x32),
// BK=32, 3-stage ring, one sync per k-tile, 2 CTAs/SM.
// ---------------------------------------------------------------------------
template<int KT>
__global__ void __launch_bounds__(256, 2)
mma_gemm_bias(const float* __restrict__ A, int lda,
              const float* __restrict__ Bt,
              const float* __restrict__ bias,
              float* __restrict__ C)
{
    constexpr int BM = 128, BN = 128, BK = 32, PAD = 36;
    constexpr int MT = 4, NT = 4;
    constexpr int SFL = (BM + BN) * PAD;

    extern __shared__ float sm[];
    const uint32_t sbase = smem_to_u32(sm);

    const int tid  = threadIdx.x;
    const int wid  = tid >> 5;
    const int lane = tid & 31;
    const int wm0  = (wid >> 2) * 64;
    const int wn0  = (wid & 3) * 32;
    const int m0   = blockIdx.y * BM;
    const int n0   = blockIdx.x * BN;
    const int K    = KT * BK;
    const int r    = lane >> 2;
    const int cq   = lane & 3;
    const int l8   = lane & 7;
    const int sid  = lane >> 3;

    uint32_t a_off[MT], b_off[2];
    #pragma unroll
    for (int mt = 0; mt < MT; mt++)
        a_off[mt] = (uint32_t)(((wm0 + mt * 16 + (sid & 1) * 8 + l8) * PAD
                                + (sid >> 1) * 4) * 4);
    #pragma unroll
    for (int p = 0; p < 2; p++)
        b_off[p] = (uint32_t)(((BM + wn0 + p * 16 + (sid >> 1) * 8 + l8) * PAD
                                + (sid & 1) * 4) * 4);

    float acc[MT][NT][4] = {};

    auto load_stage = [&](int kt) {
        const uint32_t dst = sbase + (uint32_t)(kt % 3) * (SFL * 4);
        const float* Ag = A  + (size_t)m0 * lda + kt * BK;
        const float* Bg = Bt + (size_t)n0 * K   + kt * BK;
        #pragma unroll
        for (int i = 0; i < 4; i++) {
            int cid = tid + i * 256;
            int row = cid >> 3, c = cid & 7;
            cp_async16(dst + (uint32_t)(row * PAD * 4) + c * 16,
                       Ag + (size_t)row * lda + c * 4);
        }
        #pragma unroll
        for (int i = 0; i < 4; i++) {
            int cid = tid + i * 256;
            int row = cid >> 3, c = cid & 7;
            cp_async16(dst + (uint32_t)((BM + row) * PAD * 4) + c * 16,
                       Bg + (size_t)row * K + c * 4);
        }
        asm volatile("cp.async.commit_group;\n");
    };

    load_stage(0);
    if (KT > 1) load_stage(1);

    #pragma unroll 1
    for (int kt = 0; kt < KT; kt++) {
        if (kt < KT - 1) asm volatile("cp.async.wait_group 1;\n");
        else             asm volatile("cp.async.wait_group 0;\n");
        __syncthreads();

        if (kt + 2 < KT) load_stage(kt + 2);

        const uint32_t stg = sbase + (uint32_t)(kt % 3) * (SFL * 4);

        #pragma unroll
        for (int ks = 0; ks < 4; ks++) {
            uint32_t af[MT][4], bf[NT][2];
            #pragma unroll
            for (int mt = 0; mt < MT; mt++)
                LDSM_X4(af[mt][0], af[mt][1], af[mt][2], af[mt][3],
                        stg + a_off[mt] + ks * 32);
            #pragma unroll
            for (int p = 0; p < 2; p++) {
                uint32_t q0, q1, q2, q3;
                LDSM_X4(q0, q1, q2, q3, stg + b_off[p] + ks * 32);
                bf[2 * p][0] = q0; bf[2 * p][1] = q1;
                bf[2 * p + 1][0] = q2; bf[2 * p + 1][1] = q3;
            }
            #pragma unroll
            for (int mt = 0; mt < MT; mt++)
                #pragma unroll
                for (int nt = 0; nt < NT; nt++)
                    mma_tf32_16n8k8(acc[mt][nt], af[mt], bf[nt]);
        }
    }

    #pragma unroll
    for (int mt = 0; mt < MT; mt++) {
        #pragma unroll
        for (int nt = 0; nt < NT; nt++) {
            const int row  = m0 + wm0 + mt * 16 + r;
            const int colb = n0 + wn0 + nt * 8 + cq * 2;
            float2 bv = *reinterpret_cast<const float2*>(bias + colb);
            float2 o01 = { acc[mt][nt][0] + bv.x, acc[mt][nt][1] + bv.y };
            float2 o23 = { acc[mt][nt][2] + bv.x, acc[mt][nt][3] + bv.y };
            *reinterpret_cast<float2*>(C + (size_t)row * G4 + colb)       = o01;
            *reinterpret_cast<float2*>(C + (size_t)(row + 8) * G4 + colb) = o23;
        }
    }
}

// ---------------------------------------------------------------------------
// Persistent recurrence v8.1: mbarrier full/empty ring (FIXED: .noinc arrive).
// 384 threads: warps 0-7 consumers (4m x 2n, 32x32 tiles, MT=2/NT=4,
// fragment double-buffering), warps 8-11 producers (all cp.async).
// 3 stages; full cnt=128 (producer threads, cp.async.noinc completion),
// empty cnt=256 (consumer threads). Z rides stage kt=1; c-state in regs.
// ---------------------------------------------------------------------------
template<int L1>
__global__ void __launch_bounds__(384, 1)
rec_layer(const float* __restrict__ Uw,
          const float* __restrict__ Z,
          float* __restrict__ Hbuf,
          unsigned* __restrict__ bar)
{
    constexpr int BM = 128, BN = 64, BK = 64, PAD = 68, KT = 16;
    constexpr int MT = 2, NT = 4;
    constexpr int SFL  = (BM + BN) * PAD;
    constexpr int ZOFF = 3 * SFL;
    constexpr int ZPAD = 68;
    constexpr int MBOFF_B = (3 * SFL + 128 * ZPAD) * 4;
    const size_t BH  = (size_t)BATCH * HIDDEN;
    const size_t BG4 = (size_t)BATCH * G4;

    extern __shared__ float sm[];
    const uint32_t sbase = smem_to_u32(sm);
    const uint32_t MB    = sbase + (uint32_t)MBOFF_B;     // full[0..2], empty[0..2]

    const int tid  = threadIdx.x;
    const int wid  = tid >> 5;                 // 0..11
    const int lane = tid & 31;
    const bool prod = (wid >= 8);
    const int ptid = tid - 256;                // producer-local 0..127
    const int m0   = blockIdx.y * BM;
    const int n0   = blockIdx.x * BN;
    const int r    = lane >> 2;
    const int cq   = lane & 3;
    const int l8   = lane & 7;
    const int sid  = lane >> 3;

    const int wm0  = (wid >> 1) * 32;
    const int wn0  = (wid & 1) * 32;

    uint32_t a_off[MT], b_off[2];
    #pragma unroll
    for (int mt = 0; mt < MT; mt++)
        a_off[mt] = (uint32_t)(((wm0 + mt * 16 + (sid & 1) * 8 + l8) * PAD
                                + (sid >> 1) * 4) * 4);
    #pragma unroll
    for (int p = 0; p < 2; p++)
        b_off[p] = (uint32_t)(((BM + wn0 + p * 16 + (sid >> 1) * 8 + l8) * PAD
                                + (sid & 1) * 4) * 4);

    if (tid == 0) {
        #pragma unroll
        for (int s = 0; s < 3; s++) {
            MBARRIER_INIT(MB + s * 8,      128u);   // full[s]
            MBARRIER_INIT(MB + 24 + s * 8, 256u);   // empty[s]
        }
    }
    __syncthreads();

    int fph[3] = {0, 0, 0};   // consumer: full phases
    int eph[3] = {1, 1, 1};   // producer: empty phases (fresh-barrier parity trick)

    float creg[MT * NT * 2] = {};

    #pragma unroll 1
    for (int t = 0; t < SEQ; t++) {
        const float* A    = Hbuf + (size_t)(L1 ? t : (t & 1)) * BH;
        float*       Hout = Hbuf + (size_t)(L1 ? (t + 1) : ((t + 1) & 1)) * BH;
        const float* Zt   = Z + (size_t)t * BG4;

        if (prod) {
            #pragma unroll 1
            for (int kt = 0; kt < KT; kt++) {
                const int s = kt % 3;
                MBARRIER_WAIT_PARITY(MB + 24 + s * 8, eph[s]);
                eph[s] ^= 1;
                const uint32_t dst = sbase + (uint32_t)s * (SFL * 4);
                const float* Ag = A  + (size_t)m0 * HIDDEN + kt * BK;
                const float* Bg = Uw + (size_t)n0 * HIDDEN + kt * BK;
                #pragma unroll
                for (int i = 0; i < 16; i++) {
                    int cid = ptid + i * 128;
                    int row = cid >> 4, c = cid & 15;
                    cp_async16(dst + (uint32_t)(row * PAD * 4) + c * 16,
                               Ag + (size_t)row * HIDDEN + c * 4);
                }
                #pragma unroll
                for (int i = 0; i < 8; i++) {
                    int cid = ptid + i * 128;
                    int row = cid >> 4, c = cid & 15;
                    cp_async16(dst + (uint32_t)((BM + row) * PAD * 4) + c * 16,
                               Bg + (size_t)row * HIDDEN + c * 4);
                }
                if (kt == 1) {
                    #pragma unroll
                    for (int i = 0; i < 16; i++) {
                        int cid = ptid + i * 128;
                        int row = cid >> 4, c = cid & 15;
                        cp_async16(sbase + (uint32_t)((ZOFF + row * ZPAD) * 4) + c * 16,
                                   Zt + (size_t)(m0 + row) * G4 + n0 + c * 4);
                    }
                }
                CPASYNC_MBAR_ARRIVE_NOINC(MB + s * 8);
            }
        } else {
            float acc[MT][NT][4] = {};

            #pragma unroll 1
            for (int kt = 0; kt < KT; kt++) {
                const int s = kt % 3;
                MBARRIER_WAIT_PARITY(MB + s * 8, fph[s]);
                fph[s] ^= 1;
                const uint32_t stg = sbase + (uint32_t)s * (SFL * 4);

                uint32_t af[2][MT][4], bf[2][NT][2];
                auto load_frags = [&](int ks, int b) {
                    #pragma unroll
                    for (int mt = 0; mt < MT; mt++)
                        LDSM_X4(af[b][mt][0], af[b][mt][1], af[b][mt][2], af[b][mt][3],
                                stg + a_off[mt] + ks * 32);
                    #pragma unroll
                    for (int p = 0; p < 2; p++) {
                        uint32_t q0, q1, q2, q3;
                        LDSM_X4(q0, q1, q2, q3, stg + b_off[p] + ks * 32);
                        bf[b][2 * p][0] = q0; bf[b][2 * p][1] = q1;
                        bf[b][2 * p + 1][0] = q2; bf[b][2 * p + 1][1] = q3;
                    }
                };

                load_frags(0, 0);
                #pragma unroll
                for (int ks = 0; ks < 8; ks++) {
                    const int cur = ks & 1;
                    if (ks < 7) load_frags(ks + 1, cur ^ 1);
                    #pragma unroll
                    for (int mt = 0; mt < MT; mt++)
                        #pragma unroll
                        for (int nt = 0; nt < NT; nt++)
                            mma_tf32_16n8k8(acc[mt][nt], af[cur][mt], bf[cur][nt]);
                }
                MBARRIER_ARRIVE(MB + 24 + s * 8);
            }

            // ---- fused LSTM cell epilogue (Z from smem) ----
            #pragma unroll
            for (int mt = 0; mt < MT; mt++) {
                #pragma unroll
                for (int nt = 0; nt < NT; nt++) {
                    const int rl   = wm0 + mt * 16 + r;
                    const int cl   = wn0 + nt * 8 + cq * 2;
                    float v0 = acc[mt][nt][0], v1 = acc[mt][nt][1];
                    float v2 = acc[mt][nt][2], v3 = acc[mt][nt][3];
                    float2 z01 = *reinterpret_cast<const float2*>(sm + ZOFF + rl * ZPAD + cl);
                    float2 z23 = *reinterpret_cast<const float2*>(sm + ZOFF + (rl + 8) * ZPAD + cl);
                    v0 += z01.x; v1 += z01.y; v2 += z23.x; v3 += z23.y;
                    float p0 = __shfl_xor_sync(0xffffffffu, v0, 1);
                    float p1 = __shfl_xor_sync(0xffffffffu, v1, 1);
                    float p2 = __shfl_xor_sync(0xffffffffu, v2, 1);
                    float p3 = __shfl_xor_sync(0xffffffffu, v3, 1);
                    if ((lane & 1) == 0) {
                        const int row = m0 + rl;
                        const int j   = (n0 + cl) >> 2;
                        const int ci  = (mt * NT + nt) * 2;
                        float cn = sigf(v1) * creg[ci] + sigf(v0) * tanhf(p0);
                        creg[ci] = cn;
                        Hout[(size_t)row * HIDDEN + j] = to_tf32(sigf(p1) * tanhf(cn));
                        float cn2 = sigf(v3) * creg[ci + 1] + sigf(v2) * tanhf(p2);
                        creg[ci + 1] = cn2;
                        Hout[(size_t)(row + 8) * HIDDEN + j] = to_tf32(sigf(p3) * tanhf(cn2));
                    }
                }
            }
        }

        // ---- step boundary: CTA sync + grid barrier (h dependency + Z WAR) ----
        if (t < SEQ - 1) {
            __syncthreads();
            if (tid == 0) {
                __threadfence();
                atomicAdd(&bar[t], 1u);
                volatile unsigned* p = bar + t;
                while (*p < REC_CTAS) { }
                __threadfence();
            }
            __syncthreads();
        }
    }
}

// ---------------------------------------------------------------------------
// Merged prologue: weight transpose+interleave (z<16), bias reorder + state
// zero + barrier zero (z==16).
// ---------------------------------------------------------------------------
__global__ void reorder_all(const float* __restrict__ W1, const float* __restrict__ U1,
                            const float* __restrict__ W2, const float* __restrict__ U2,
                            const float* __restrict__ b1, const float* __restrict__ b2,
                            float* __restrict__ W1r, float* __restrict__ U1T,
                            float* __restrict__ W2r, float* __restrict__ U2T,
                            float* __restrict__ b1r, float* __restrict__ b2r,
                            float* __restrict__ H1_0, float* __restrict__ h2_0,
                            unsigned* __restrict__ bar1, unsigned* __restrict__ bar2)
{
    const int z = blockIdx.z;
    if (z == 16) {
        int flat = (blockIdx.x * 32 + blockIdx.y) * 1024 + threadIdx.y * 32 + threadIdx.x;
        if (flat < G4)           b1r[flat] = b1[(flat & 3) * HIDDEN + (flat >> 2)];
        else if (flat < 2 * G4) { int m = flat - G4; b2r[m] = b2[(m & 3) * HIDDEN + (m >> 2)]; }
        if (flat < BATCH * HIDDEN) { H1_0[flat] = 0.f; h2_0[flat] = 0.f; }
        if (flat < SEQ) { bar1[flat] = 0u; bar2[flat] = 0u; }
        return;
    }
    __shared__ float tile[32][33];
    const int mi = z >> 2, g = z & 3;
    const int K  = (mi == 0) ? INPUT : HIDDEN;
    const int k0 = blockIdx.x * 32;
    if (k0 >= K) return;
    const int j0 = blockIdx.y * 32;
    const float* in  = (mi == 0) ? W1 : (mi == 1) ? U1 : (mi == 2) ? W2 : U2;
    float*       out = (mi == 0) ? W1r : (mi == 1) ? U1T : (mi == 2) ? W2r : U2T;
    const int tx = threadIdx.x, ty = threadIdx.y;
    tile[ty][tx] = in[(size_t)(k0 + ty) * G4 + g * HIDDEN + j0 + tx];
    __syncthreads();
    out[(size_t)(4 * (j0 + ty) + g) * K + k0 + tx] = to_tf32(tile[tx][ty]);
}

// ---------------------------------------------------------------------------
// Pack x: [B, S, I] -> [S*B, I]  (row m = t*B + b), tf32-rounded
// ---------------------------------------------------------------------------
__global__ void pack_x_kernel(const float4* __restrict__ x, float4* __restrict__ xp) {
    int n = blockIdx.x * blockDim.x + threadIdx.x;
    const int I4 = INPUT / 4;
    int k = n % I4;
    int rr = n / I4;
    int b = rr % BATCH;
    int t = rr / BATCH;
    float4 v = x[((size_t)b * SEQ + t) * I4 + k];
    v.x = to_tf32(v.x); v.y = to_tf32(v.y); v.z = to_tf32(v.z); v.w = to_tf32(v.w);
    xp[n] = v;
}

// ---------------------------------------------------------------------------
// Final projection (M=256, N=1000, K=1024) — scalar fp32 (exact)
// ---------------------------------------------------------------------------
__global__ void final_proj_kernel(const float* __restrict__ A,
                                  const float* __restrict__ B,
                                  const float* __restrict__ bias,
                                  float* __restrict__ C)
{
    constexpr int BM = 64, BN = 64, BK = 16, TM = 4, TN = 4, TX = 16;
    __shared__ float As[BK][BM];
    __shared__ float Bs[BK][BN];
    const int tid  = threadIdx.x;
    const int tx   = tid % TX;
    const int ty   = tid / TX;
    const int brow = blockIdx.y * BM;
    const int bcol = blockIdx.x * BN;
    float acc[TM][TN] = {};

    for (int kt = 0; kt < HIDDEN; kt += BK) {
        {
            int ar = tid / (BK / 4);
            int ak = (tid % (BK / 4)) * 4;
            float4 v = *reinterpret_cast<const float4*>(A + (size_t)(brow + ar) * HIDDEN + kt + ak);
            As[ak + 0][ar] = v.x; As[ak + 1][ar] = v.y; As[ak + 2][ar] = v.z; As[ak + 3][ar] = v.w;
        }
        {
            int bk = tid / (BN / 4);
            int bn = (tid % (BN / 4)) * 4;
            int col = bcol + bn;
            const float* src = B + (size_t)(kt + bk) * CLASSES + col;
            Bs[bk][bn + 0] = (col + 0 < CLASSES) ? src[0] : 0.f;
            Bs[bk][bn + 1] = (col + 1 < CLASSES) ? src[1] : 0.f;
            Bs[bk][bn + 2] = (col + 2 < CLASSES) ? src[2] : 0.f;
            Bs[bk][bn + 3] = (col + 3 < CLASSES) ? src[3] : 0.f;
        }
        __syncthreads();
        #pragma unroll
        for (int k = 0; k < BK; k++) {
            float ra[TM], rb[TN];
            #pragma unroll
            for (int i = 0; i < TM; i++) ra[i] = As[k][ty * TM + i];
            #pragma unroll
            for (int j = 0; j < TN; j++) rb[j] = Bs[k][tx * TN + j];
            #pragma unroll
            for (int i = 0; i < TM; i++)
                #pragma unroll
                for (int j = 0; j < TN; j++)
                    acc[i][j] += ra[i] * rb[j];
        }
        __syncthreads();
    }
    #pragma unroll
    for (int i = 0; i < TM; i++) {
        int rr = brow + ty * TM + i;
        #pragma unroll
        for (int j = 0; j < TN; j++) {
            int col = bcol + tx * TN + j;
            if (col < CLASSES)
                C[(size_t)rr * CLASSES + col] = acc[i][j] + bias[col];
        }
    }
}

// ---------------------------------------------------------------------------
// Launch (7 nodes; launch #4 = rec_layer<1> v8.1 for ncu capture)
// ---------------------------------------------------------------------------
extern "C" void kernel_launch(void* const* d_in, const int* in_sizes, int n_in,
                              void* d_out, int out_size)
{
    const float* x  = (const float*)d_in[0];
    const float* W1 = (const float*)d_in[1];
    const float* U1 = (const float*)d_in[2];
    const float* b1 = (const float*)d_in[3];
    const float* W2 = (const float*)d_in[4];
    const float* U2 = (const float*)d_in[5];
    const float* b2 = (const float*)d_in[6];
    const float* Wo = (const float*)d_in[7];
    const float* bo = (const float*)d_in[8];
    float* out = (float*)d_out;

    float *X, *Z, *H1, *h2, *W1r, *U1T, *W2r, *U2T, *b1r, *b2r;
    unsigned *bar1, *bar2;
    cudaGetSymbolAddress((void**)&X,   g_X);
    cudaGetSymbolAddress((void**)&Z,   g_Z);
    cudaGetSymbolAddress((void**)&H1,  g_H1);
    cudaGetSymbolAddress((void**)&h2,  g_h2);
    cudaGetSymbolAddress((void**)&W1r, g_W1r);
    cudaGetSymbolAddress((void**)&U1T, g_U1T);
    cudaGetSymbolAddress((void**)&W2r, g_W2r);
    cudaGetSymbolAddress((void**)&U2T, g_U2T);
    cudaGetSymbolAddress((void**)&b1r, g_b1r);
    cudaGetSymbolAddress((void**)&b2r, g_b2r);
    cudaGetSymbolAddress((void**)&bar1, g_bar1);
    cudaGetSymbolAddress((void**)&bar2, g_bar2);

    const int SMEM_BIG = 3 * (128 + 128) * 36 * 4;                         // 110592
    const int SMEM_REC = (3 * (128 + 64) * 68 + 128 * 68) * 4 + 64;        // +mbarriers
    cudaFuncSetAttribute(mma_gemm_bias<16>, cudaFuncAttributeMaxDynamicSharedMemorySize, SMEM_BIG);
    cudaFuncSetAttribute(mma_gemm_bias<32>, cudaFuncAttributeMaxDynamicSharedMemorySize, SMEM_BIG);
    cudaFuncSetAttribute(rec_layer<1>, cudaFuncAttributeMaxDynamicSharedMemorySize, SMEM_REC);
    cudaFuncSetAttribute(rec_layer<0>, cudaFuncAttributeMaxDynamicSharedMemorySize, SMEM_REC);

    const size_t BH = (size_t)BATCH * HIDDEN;

    // 1) reorder weights + biases + state/barrier init (merged)
    reorder_all<<<dim3(32, 32, 17), dim3(32, 32)>>>(W1, U1, W2, U2, b1, b2,
                                                    W1r, U1T, W2r, U2T, b1r, b2r,
                                                    H1, h2, bar1, bar2);
    // 2) pack X
    pack_x_kernel<<<SB * INPUT / 4 / 256, 256>>>((const float4*)x, (float4*)X);
    // 3) Z = X @ W1r^T + b1r  (K=512, KT=16)
    mma_gemm_bias<16><<<dim3(G4 / 128, SB / 128), 256, SMEM_BIG>>>(X, INPUT, W1r, b1r, Z);
    // 4) layer-1 recurrence v8.1 (mbarrier ring, .noinc)   <-- ncu capture slot
    rec_layer<1><<<dim3(64, 2), 384, SMEM_REC>>>(U1T, Z, H1, bar1);
    // 5) Z = H1[1..64] @ W2r^T + b2r  (K=1024, KT=32)
    mma_gemm_bias<32><<<dim3(G4 / 128, SB / 128), 256, SMEM_BIG>>>(H1 + BH, HIDDEN, W2r, b2r, Z);
    // 6) layer-2 recurrence v8.1
    rec_layer<0><<<dim3(64, 2), 384, SMEM_REC>>>(U2T, Z, h2, bar2);
    // 7) out = h2[0] @ Wo + bo
    final_proj_kernel<<<dim3((CLASSES + 63) / 64, BATCH / 64), 256>>>(h2, Wo, bo, out);
}

// round 17
// speedup vs baseline: 1.3031x; 1.0904x over previous
#include <cuda_runtime.h>
#include <cstdint>
#include <cstddef>

#define BATCH   256
#define SEQ     64
#define INPUT   512
#define HIDDEN  1024
#define CLASSES 1000
#define SB      (SEQ * BATCH)   // 16384
#define G4      (4 * HIDDEN)    // 4096
#define REC_CTAS 128u

// ---------------------------------------------------------------------------
// Scratch (device globals — no allocations allowed)
// ---------------------------------------------------------------------------
__device__ float g_X  [SB * INPUT];
__device__ float g_Z  [(size_t)SB * G4];
__device__ float g_H1 [(SEQ + 1) * BATCH * HIDDEN];
__device__ float g_h2 [2 * BATCH * HIDDEN];
__device__ float g_W1r[(size_t)G4 * INPUT];
__device__ float g_U1T[(size_t)G4 * HIDDEN];
__device__ float g_W2r[(size_t)G4 * HIDDEN];
__device__ float g_U2T[(size_t)G4 * HIDDEN];
__device__ float g_b1r[G4];
__device__ float g_b2r[G4];
__device__ unsigned g_bar1[SEQ];
__device__ unsigned g_bar2[SEQ];

// ---------------------------------------------------------------------------
// Helpers
// ---------------------------------------------------------------------------
__device__ __forceinline__ uint32_t smem_to_u32(const void* p) {
    uint32_t a;
    asm("{ .reg .u64 t; cvta.to.shared.u64 t, %1; cvt.u32.u64 %0, t; }"
        : "=r"(a) : "l"(p));
    return a;
}

__device__ __forceinline__ float to_tf32(float x) {
    uint32_t r;
    asm("cvt.rna.tf32.f32 %0, %1;" : "=r"(r) : "f"(x));
    return __uint_as_float(r);
}

__device__ __forceinline__ void cp_async16(uint32_t smem_dst, const void* gmem_src) {
    asm volatile("cp.async.cg.shared.global [%0], [%1], 16;\n" :: "r"(smem_dst), "l"(gmem_src));
}

__device__ __forceinline__ void mma_tf32_16n8k8(float* d, const uint32_t* a, const uint32_t* b) {
    asm volatile(
        "mma.sync.aligned.m16n8k8.row.col.f32.tf32.tf32.f32 "
        "{%0,%1,%2,%3}, {%4,%5,%6,%7}, {%8,%9}, {%0,%1,%2,%3};"
        : "+f"(d[0]), "+f"(d[1]), "+f"(d[2]), "+f"(d[3])
        : "r"(a[0]), "r"(a[1]), "r"(a[2]), "r"(a[3]), "r"(b[0]), "r"(b[1]));
}

#define LDSM_X4(r0, r1, r2, r3, addr) \
    asm volatile("ldmatrix.sync.aligned.m8n8.x4.shared.b16 {%0,%1,%2,%3}, [%4];" \
        : "=r"(r0), "=r"(r1), "=r"(r2), "=r"(r3) : "r"(addr))

#define MBARRIER_INIT(addr, cnt) \
    asm volatile("mbarrier.init.shared.b64 [%0], %1;" :: "r"((uint32_t)(addr)), "r"((uint32_t)(cnt)) : "memory")

#define MBARRIER_ARRIVE(addr) \
    asm volatile("mbarrier.arrive.shared.b64 _, [%0];" :: "r"((uint32_t)(addr)) : "memory")

#define CPASYNC_MBAR_ARRIVE_NOINC(addr) \
    asm volatile("cp.async.mbarrier.arrive.noinc.shared.b64 [%0];" :: "r"((uint32_t)(addr)) : "memory")

#define MBARRIER_WAIT_PARITY(mbar_smem_addr, phase_parity) do { \
    uint32_t _mbar = (uint32_t)(mbar_smem_addr); \
    uint32_t _parity = (uint32_t)(phase_parity); \
    uint32_t _done; \
    asm volatile( \
        "{\n\t.reg .pred p;\n\t" \
        "mbarrier.try_wait.parity.acquire.cta.shared::cta.b64 p, [%1], %2;\n\t" \
        "selp.b32 %0, 1, 0, p;\n\t}" \
        : "=r"(_done) : "r"(_mbar), "r"(_parity) : "memory"); \
    if (!_done) { \
        asm volatile( \
            "{\n\t.reg .pred P1;\n\t" \
            "WAIT_LOOP_%=:\n\t" \
            "mbarrier.try_wait.parity.acquire.cta.shared::cta.b64 P1, [%0], %1, 0x989680;\n\t" \
            "@P1 bra.uni WAIT_DONE_%=;\n\t" \
            "bra.uni WAIT_LOOP_%=;\n\t" \
            "WAIT_DONE_%=:\n\t}" \
            :: "r"(_mbar), "r"(_parity) : "memory"); \
    } \
} while(0)

// Fast activations: flag-independent approx exp (MUFU.EX2) + fast divide.
__device__ __forceinline__ float fexp(float x) {
    float y;
    asm("ex2.approx.ftz.f32 %0, %1;" : "=f"(y) : "f"(x * 1.4426950408889634f));
    return y;
}
__device__ __forceinline__ float fsig(float x)  { return __fdividef(1.f, 1.f + fexp(-x)); }
__device__ __forceinline__ float ftanh(float x) { return __fdividef(2.f, 1.f + fexp(-2.f * x)) - 1.f; }
__device__ __forceinline__ float sigf(float x)  { return 1.f / (1.f + expf(-x)); }

// ---------------------------------------------------------------------------
// Big GEMM v3 (UNCHANGED — protected win): 256 thr / 8 warps (2m x 4n, 64x32),
// BK=32, 3-stage ring, one sync per k-tile, 2 CTAs/SM.
// ---------------------------------------------------------------------------
template<int KT>
__global__ void __launch_bounds__(256, 2)
mma_gemm_bias(const float* __restrict__ A, int lda,
              const float* __restrict__ Bt,
              const float* __restrict__ bias,
              float* __restrict__ C)
{
    constexpr int BM = 128, BN = 128, BK = 32, PAD = 36;
    constexpr int MT = 4, NT = 4;
    constexpr int SFL = (BM + BN) * PAD;

    extern __shared__ float sm[];
    const uint32_t sbase = smem_to_u32(sm);

    const int tid  = threadIdx.x;
    const int wid  = tid >> 5;
    const int lane = tid & 31;
    const int wm0  = (wid >> 2) * 64;
    const int wn0  = (wid & 3) * 32;
    const int m0   = blockIdx.y * BM;
    const int n0   = blockIdx.x * BN;
    const int K    = KT * BK;
    const int r    = lane >> 2;
    const int cq   = lane & 3;
    const int l8   = lane & 7;
    const int sid  = lane >> 3;

    uint32_t a_off[MT], b_off[2];
    #pragma unroll
    for (int mt = 0; mt < MT; mt++)
        a_off[mt] = (uint32_t)(((wm0 + mt * 16 + (sid & 1) * 8 + l8) * PAD
                                + (sid >> 1) * 4) * 4);
    #pragma unroll
    for (int p = 0; p < 2; p++)
        b_off[p] = (uint32_t)(((BM + wn0 + p * 16 + (sid >> 1) * 8 + l8) * PAD
                                + (sid & 1) * 4) * 4);

    float acc[MT][NT][4] = {};

    auto load_stage = [&](int kt) {
        const uint32_t dst = sbase + (uint32_t)(kt % 3) * (SFL * 4);
        const float* Ag = A  + (size_t)m0 * lda + kt * BK;
        const float* Bg = Bt + (size_t)n0 * K   + kt * BK;
        #pragma unroll
        for (int i = 0; i < 4; i++) {
            int cid = tid + i * 256;
            int row = cid >> 3, c = cid & 7;
            cp_async16(dst + (uint32_t)(row * PAD * 4) + c * 16,
                       Ag + (size_t)row * lda + c * 4);
        }
        #pragma unroll
        for (int i = 0; i < 4; i++) {
            int cid = tid + i * 256;
            int row = cid >> 3, c = cid & 7;
            cp_async16(dst + (uint32_t)((BM + row) * PAD * 4) + c * 16,
                       Bg + (size_t)row * K + c * 4);
        }
        asm volatile("cp.async.commit_group;\n");
    };

    load_stage(0);
    if (KT > 1) load_stage(1);

    #pragma unroll 1
    for (int kt = 0; kt < KT; kt++) {
        if (kt < KT - 1) asm volatile("cp.async.wait_group 1;\n");
        else             asm volatile("cp.async.wait_group 0;\n");
        __syncthreads();

        if (kt + 2 < KT) load_stage(kt + 2);

        const uint32_t stg = sbase + (uint32_t)(kt % 3) * (SFL * 4);

        #pragma unroll
        for (int ks = 0; ks < 4; ks++) {
            uint32_t af[MT][4], bf[NT][2];
            #pragma unroll
            for (int mt = 0; mt < MT; mt++)
                LDSM_X4(af[mt][0], af[mt][1], af[mt][2], af[mt][3],
                        stg + a_off[mt] + ks * 32);
            #pragma unroll
            for (int p = 0; p < 2; p++) {
                uint32_t q0, q1, q2, q3;
                LDSM_X4(q0, q1, q2, q3, stg + b_off[p] + ks * 32);
                bf[2 * p][0] = q0; bf[2 * p][1] = q1;
                bf[2 * p + 1][0] = q2; bf[2 * p + 1][1] = q3;
            }
            #pragma unroll
            for (int mt = 0; mt < MT; mt++)
                #pragma unroll
                for (int nt = 0; nt < NT; nt++)
                    mma_tf32_16n8k8(acc[mt][nt], af[mt], bf[nt]);
        }
    }

    #pragma unroll
    for (int mt = 0; mt < MT; mt++) {
        #pragma unroll
        for (int nt = 0; nt < NT; nt++) {
            const int row  = m0 + wm0 + mt * 16 + r;
            const int colb = n0 + wn0 + nt * 8 + cq * 2;
            float2 bv = *reinterpret_cast<const float2*>(bias + colb);
            float2 o01 = { acc[mt][nt][0] + bv.x, acc[mt][nt][1] + bv.y };
            float2 o23 = { acc[mt][nt][2] + bv.x, acc[mt][nt][3] + bv.y };
            *reinterpret_cast<float2*>(C + (size_t)row * G4 + colb)       = o01;
            *reinterpret_cast<float2*>(C + (size_t)(row + 8) * G4 + colb) = o23;
        }
    }
}

// ---------------------------------------------------------------------------
// Persistent recurrence v8.2: mbarrier ring (round-16 win) + fast epilogue:
// even lane computes row, odd lane computes row+8 (full-warp cell math),
// approx-exp activations, c-state 1 reg per (mt,nt) per lane.
// ---------------------------------------------------------------------------
template<int L1>
__global__ void __launch_bounds__(384, 1)
rec_layer(const float* __restrict__ Uw,
          const float* __restrict__ Z,
          float* __restrict__ Hbuf,
          unsigned* __restrict__ bar)
{
    constexpr int BM = 128, BN = 64, BK = 64, PAD = 68, KT = 16;
    constexpr int MT = 2, NT = 4;
    constexpr int SFL  = (BM + BN) * PAD;
    constexpr int ZOFF = 3 * SFL;
    constexpr int ZPAD = 68;
    constexpr int MBOFF_B = (3 * SFL + 128 * ZPAD) * 4;
    const size_t BH  = (size_t)BATCH * HIDDEN;
    const size_t BG4 = (size_t)BATCH * G4;

    extern __shared__ float sm[];
    const uint32_t sbase = smem_to_u32(sm);
    const uint32_t MB    = sbase + (uint32_t)MBOFF_B;     // full[0..2], empty[0..2]

    const int tid  = threadIdx.x;
    const int wid  = tid >> 5;                 // 0..11
    const int lane = tid & 31;
    const bool prod = (wid >= 8);
    const int ptid = tid - 256;                // producer-local 0..127
    const int m0   = blockIdx.y * BM;
    const int n0   = blockIdx.x * BN;
    const int r    = lane >> 2;
    const int cq   = lane & 3;
    const int l8   = lane & 7;
    const int sid  = lane >> 3;
    const int odd  = lane & 1;

    const int wm0  = (wid >> 1) * 32;
    const int wn0  = (wid & 1) * 32;

    uint32_t a_off[MT], b_off[2];
    #pragma unroll
    for (int mt = 0; mt < MT; mt++)
        a_off[mt] = (uint32_t)(((wm0 + mt * 16 + (sid & 1) * 8 + l8) * PAD
                                + (sid >> 1) * 4) * 4);
    #pragma unroll
    for (int p = 0; p < 2; p++)
        b_off[p] = (uint32_t)(((BM + wn0 + p * 16 + (sid >> 1) * 8 + l8) * PAD
                                + (sid & 1) * 4) * 4);

    if (tid == 0) {
        #pragma unroll
        for (int s = 0; s < 3; s++) {
            MBARRIER_INIT(MB + s * 8,      128u);   // full[s]
            MBARRIER_INIT(MB + 24 + s * 8, 256u);   // empty[s]
        }
    }
    __syncthreads();

    int fph[3] = {0, 0, 0};
    int eph[3] = {1, 1, 1};

    float creg[MT * NT] = {};    // c-state: one per (mt,nt); even lane = row, odd = row+8

    #pragma unroll 1
    for (int t = 0; t < SEQ; t++) {
        const float* A    = Hbuf + (size_t)(L1 ? t : (t & 1)) * BH;
        float*       Hout = Hbuf + (size_t)(L1 ? (t + 1) : ((t + 1) & 1)) * BH;
        const float* Zt   = Z + (size_t)t * BG4;

        if (prod) {
            #pragma unroll 1
            for (int kt = 0; kt < KT; kt++) {
                const int s = kt % 3;
                MBARRIER_WAIT_PARITY(MB + 24 + s * 8, eph[s]);
                eph[s] ^= 1;
                const uint32_t dst = sbase + (uint32_t)s * (SFL * 4);
                const float* Ag = A  + (size_t)m0 * HIDDEN + kt * BK;
                const float* Bg = Uw + (size_t)n0 * HIDDEN + kt * BK;
                #pragma unroll
                for (int i = 0; i < 16; i++) {
                    int cid = ptid + i * 128;
                    int row = cid >> 4, c = cid & 15;
                    cp_async16(dst + (uint32_t)(row * PAD * 4) + c * 16,
                               Ag + (size_t)row * HIDDEN + c * 4);
                }
                #pragma unroll
                for (int i = 0; i < 8; i++) {
                    int cid = ptid + i * 128;
                    int row = cid >> 4, c = cid & 15;
                    cp_async16(dst + (uint32_t)((BM + row) * PAD * 4) + c * 16,
                               Bg + (size_t)row * HIDDEN + c * 4);
                }
                if (kt == 1) {
                    #pragma unroll
                    for (int i = 0; i < 16; i++) {
                        int cid = ptid + i * 128;
                        int row = cid >> 4, c = cid & 15;
                        cp_async16(sbase + (uint32_t)((ZOFF + row * ZPAD) * 4) + c * 16,
                                   Zt + (size_t)(m0 + row) * G4 + n0 + c * 4);
                    }
                }
                CPASYNC_MBAR_ARRIVE_NOINC(MB + s * 8);
            }
        } else {
            float acc[MT][NT][4] = {};

            #pragma unroll 1
            for (int kt = 0; kt < KT; kt++) {
                const int s = kt % 3;
                MBARRIER_WAIT_PARITY(MB + s * 8, fph[s]);
                fph[s] ^= 1;
                const uint32_t stg = sbase + (uint32_t)s * (SFL * 4);

                uint32_t af[2][MT][4], bf[2][NT][2];
                auto load_frags = [&](int ks, int b) {
                    #pragma unroll
                    for (int mt = 0; mt < MT; mt++)
                        LDSM_X4(af[b][mt][0], af[b][mt][1], af[b][mt][2], af[b][mt][3],
                                stg + a_off[mt] + ks * 32);
                    #pragma unroll
                    for (int p = 0; p < 2; p++) {
                        uint32_t q0, q1, q2, q3;
                        LDSM_X4(q0, q1, q2, q3, stg + b_off[p] + ks * 32);
                        bf[b][2 * p][0] = q0; bf[b][2 * p][1] = q1;
                        bf[b][2 * p + 1][0] = q2; bf[b][2 * p + 1][1] = q3;
                    }
                };

                load_frags(0, 0);
                #pragma unroll
                for (int ks = 0; ks < 8; ks++) {
                    const int cur = ks & 1;
                    if (ks < 7) load_frags(ks + 1, cur ^ 1);
                    #pragma unroll
                    for (int mt = 0; mt < MT; mt++)
                        #pragma unroll
                        for (int nt = 0; nt < NT; nt++)
                            mma_tf32_16n8k8(acc[mt][nt], af[cur][mt], bf[cur][nt]);
                }
                MBARRIER_ARRIVE(MB + 24 + s * 8);
            }

            // ---- fused LSTM cell epilogue (Z from smem; full-warp split) ----
            // Lane pair (2k, 2k+1): even holds (i,f) cols, odd holds (g,o) cols.
            // After shfl_xor(1) each lane has a full quad: even computes row,
            // odd computes row+8. One c reg per (mt,nt) per lane.
            #pragma unroll
            for (int mt = 0; mt < MT; mt++) {
                #pragma unroll
                for (int nt = 0; nt < NT; nt++) {
                    const int rl = wm0 + mt * 16 + r;
                    const int cl = wn0 + nt * 8 + cq * 2;
                    float v0 = acc[mt][nt][0], v1 = acc[mt][nt][1];
                    float v2 = acc[mt][nt][2], v3 = acc[mt][nt][3];
                    float2 z01 = *reinterpret_cast<const float2*>(sm + ZOFF + rl * ZPAD + cl);
                    float2 z23 = *reinterpret_cast<const float2*>(sm + ZOFF + (rl + 8) * ZPAD + cl);
                    v0 += z01.x; v1 += z01.y; v2 += z23.x; v3 += z23.y;
                    float p0 = __shfl_xor_sync(0xffffffffu, v0, 1);
                    float p1 = __shfl_xor_sync(0xffffffffu, v1, 1);
                    float p2 = __shfl_xor_sync(0xffffffffu, v2, 1);
                    float p3 = __shfl_xor_sync(0xffffffffu, v3, 1);
                    // even lane: i=v0 f=v1 g=p0 o=p1  (row rl)
                    // odd lane:  i=p2 f=p3 g=v2 o=v3  (row rl+8)
                    float zi = odd ? p2 : v0;
                    float zf = odd ? p3 : v1;
                    float zg = odd ? v2 : p0;
                    float zo = odd ? v3 : p1;
                    const int rowg = m0 + rl + (odd ? 8 : 0);
                    const int j    = (n0 + wn0 + nt * 8 + (cq & ~1) * 2) >> 2;
                    const int ci   = mt * NT + nt;
                    float cn = fsig(zf) * creg[ci] + fsig(zi) * ftanh(zg);
                    creg[ci] = cn;
                    Hout[(size_t)rowg * HIDDEN + j] = to_tf32(fsig(zo) * ftanh(cn));
                }
            }
        }

        // ---- step boundary: CTA sync + grid barrier ----
        if (t < SEQ - 1) {
            __syncthreads();
            if (tid == 0) {
                __threadfence();
                atomicAdd(&bar[t], 1u);
                volatile unsigned* p = bar + t;
                while (*p < REC_CTAS) { }
                __threadfence();
            }
            __syncthreads();
        }
    }
}

// ---------------------------------------------------------------------------
// Merged prologue: weight transpose+interleave (z<16), bias reorder + state
// zero + barrier zero (z==16).
// ---------------------------------------------------------------------------
__global__ void reorder_all(const float* __restrict__ W1, const float* __restrict__ U1,
                            const float* __restrict__ W2, const float* __restrict__ U2,
                            const float* __restrict__ b1, const float* __restrict__ b2,
                            float* __restrict__ W1r, float* __restrict__ U1T,
                            float* __restrict__ W2r, float* __restrict__ U2T,
                            float* __restrict__ b1r, float* __restrict__ b2r,
                            float* __restrict__ H1_0, float* __restrict__ h2_0,
                            unsigned* __restrict__ bar1, unsigned* __restrict__ bar2)
{
    const int z = blockIdx.z;
    if (z == 16) {
        int flat = (blockIdx.x * 32 + blockIdx.y) * 1024 + threadIdx.y * 32 + threadIdx.x;
        if (flat < G4)           b1r[flat] = b1[(flat & 3) * HIDDEN + (flat >> 2)];
        else if (flat < 2 * G4) { int m = flat - G4; b2r[m] = b2[(m & 3) * HIDDEN + (m >> 2)]; }
        if (flat < BATCH * HIDDEN) { H1_0[flat] = 0.f; h2_0[flat] = 0.f; }
        if (flat < SEQ) { bar1[flat] = 0u; bar2[flat] = 0u; }
        return;
    }
    __shared__ float tile[32][33];
    const int mi = z >> 2, g = z & 3;
    const int K  = (mi == 0) ? INPUT : HIDDEN;
    const int k0 = blockIdx.x * 32;
    if (k0 >= K) return;
    const int j0 = blockIdx.y * 32;
    const float* in  = (mi == 0) ? W1 : (mi == 1) ? U1 : (mi == 2) ? W2 : U2;
    float*       out = (mi == 0) ? W1r : (mi == 1) ? U1T : (mi == 2) ? W2r : U2T;
    const int tx = threadIdx.x, ty = threadIdx.y;
    tile[ty][tx] = in[(size_t)(k0 + ty) * G4 + g * HIDDEN + j0 + tx];
    __syncthreads();
    out[(size_t)(4 * (j0 + ty) + g) * K + k0 + tx] = to_tf32(tile[tx][ty]);
}

// ---------------------------------------------------------------------------
// Pack x: [B, S, I] -> [S*B, I]  (row m = t*B + b), tf32-rounded
// ---------------------------------------------------------------------------
__global__ void pack_x_kernel(const float4* __restrict__ x, float4* __restrict__ xp) {
    int n = blockIdx.x * blockDim.x + threadIdx.x;
    const int I4 = INPUT / 4;
    int k = n % I4;
    int rr = n / I4;
    int b = rr % BATCH;
    int t = rr / BATCH;
    float4 v = x[((size_t)b * SEQ + t) * I4 + k];
    v.x = to_tf32(v.x); v.y = to_tf32(v.y); v.z = to_tf32(v.z); v.w = to_tf32(v.w);
    xp[n] = v;
}

// ---------------------------------------------------------------------------
// Final projection (M=256, N=1000, K=1024) — scalar fp32 (exact)
// ---------------------------------------------------------------------------
__global__ void final_proj_kernel(const float* __restrict__ A,
                                  const float* __restrict__ B,
                                  const float* __restrict__ bias,
                                  float* __restrict__ C)
{
    constexpr int BM = 64, BN = 64, BK = 16, TM = 4, TN = 4, TX = 16;
    __shared__ float As[BK][BM];
    __shared__ float Bs[BK][BN];
    const int tid  = threadIdx.x;
    const int tx   = tid % TX;
    const int ty   = tid / TX;
    const int brow = blockIdx.y * BM;
    const int bcol = blockIdx.x * BN;
    float acc[TM][TN] = {};

    for (int kt = 0; kt < HIDDEN; kt += BK) {
        {
            int ar = tid / (BK / 4);
            int ak = (tid % (BK / 4)) * 4;
            float4 v = *reinterpret_cast<const float4*>(A + (size_t)(brow + ar) * HIDDEN + kt + ak);
            As[ak + 0][ar] = v.x; As[ak + 1][ar] = v.y; As[ak + 2][ar] = v.z; As[ak + 3][ar] = v.w;
        }
        {
            int bk = tid / (BN / 4);
            int bn = (tid % (BN / 4)) * 4;
            int col = bcol + bn;
            const float* src = B + (size_t)(kt + bk) * CLASSES + col;
            Bs[bk][bn + 0] = (col + 0 < CLASSES) ? src[0] : 0.f;
            Bs[bk][bn + 1] = (col + 1 < CLASSES) ? src[1] : 0.f;
            Bs[bk][bn + 2] = (col + 2 < CLASSES) ? src[2] : 0.f;
            Bs[bk][bn + 3] = (col + 3 < CLASSES) ? src[3] : 0.f;
        }
        __syncthreads();
        #pragma unroll
        for (int k = 0; k < BK; k++) {
            float ra[TM], rb[TN];
            #pragma unroll
            for (int i = 0; i < TM; i++) ra[i] = As[k][ty * TM + i];
            #pragma unroll
            for (int j = 0; j < TN; j++) rb[j] = Bs[k][tx * TN + j];
            #pragma unroll
            for (int i = 0; i < TM; i++)
                #pragma unroll
                for (int j = 0; j < TN; j++)
                    acc[i][j] += ra[i] * rb[j];
        }
        __syncthreads();
    }
    #pragma unroll
    for (int i = 0; i < TM; i++) {
        int rr = brow + ty * TM + i;
        #pragma unroll
        for (int j = 0; j < TN; j++) {
            int col = bcol + tx * TN + j;
            if (col < CLASSES)
                C[(size_t)rr * CLASSES + col] = acc[i][j] + bias[col];
        }
    }
}

// ---------------------------------------------------------------------------
// Launch (7 nodes; launch #4 = rec_layer<1> v8.2 for ncu capture)
// ---------------------------------------------------------------------------
extern "C" void kernel_launch(void* const* d_in, const int* in_sizes, int n_in,
                              void* d_out, int out_size)
{
    const float* x  = (const float*)d_in[0];
    const float* W1 = (const float*)d_in[1];
    const float* U1 = (const float*)d_in[2];
    const float* b1 = (const float*)d_in[3];
    const float* W2 = (const float*)d_in[4];
    const float* U2 = (const float*)d_in[5];
    const float* b2 = (const float*)d_in[6];
    const float* Wo = (const float*)d_in[7];
    const float* bo = (const float*)d_in[8];
    float* out = (float*)d_out;

    float *X, *Z, *H1, *h2, *W1r, *U1T, *W2r, *U2T, *b1r, *b2r;
    unsigned *bar1, *bar2;
    cudaGetSymbolAddress((void**)&X,   g_X);
    cudaGetSymbolAddress((void**)&Z,   g_Z);
    cudaGetSymbolAddress((void**)&H1,  g_H1);
    cudaGetSymbolAddress((void**)&h2,  g_h2);
    cudaGetSymbolAddress((void**)&W1r, g_W1r);
    cudaGetSymbolAddress((void**)&U1T, g_U1T);
    cudaGetSymbolAddress((void**)&W2r, g_W2r);
    cudaGetSymbolAddress((void**)&U2T, g_U2T);
    cudaGetSymbolAddress((void**)&b1r, g_b1r);
    cudaGetSymbolAddress((void**)&b2r, g_b2r);
    cudaGetSymbolAddress((void**)&bar1, g_bar1);
    cudaGetSymbolAddress((void**)&bar2, g_bar2);

    const int SMEM_BIG = 3 * (128 + 128) * 36 * 4;                         // 110592
    const int SMEM_REC = (3 * (128 + 64) * 68 + 128 * 68) * 4 + 64;        // +mbarriers
    cudaFuncSetAttribute(mma_gemm_bias<16>, cudaFuncAttributeMaxDynamicSharedMemorySize, SMEM_BIG);
    cudaFuncSetAttribute(mma_gemm_bias<32>, cudaFuncAttributeMaxDynamicSharedMemorySize, SMEM_BIG);
    cudaFuncSetAttribute(rec_layer<1>, cudaFuncAttributeMaxDynamicSharedMemorySize, SMEM_REC);
    cudaFuncSetAttribute(rec_layer<0>, cudaFuncAttributeMaxDynamicSharedMemorySize, SMEM_REC);

    const size_t BH = (size_t)BATCH * HIDDEN;

    // 1) reorder weights + biases + state/barrier init (merged)
    reorder_all<<<dim3(32, 32, 17), dim3(32, 32)>>>(W1, U1, W2, U2, b1, b2,
                                                    W1r, U1T, W2r, U2T, b1r, b2r,
                                                    H1, h2, bar1, bar2);
    // 2) pack X
    pack_x_kernel<<<SB * INPUT / 4 / 256, 256>>>((const float4*)x, (float4*)X);
    // 3) Z = X @ W1r^T + b1r  (K=512, KT=16)
    mma_gemm_bias<16><<<dim3(G4 / 128, SB / 128), 256, SMEM_BIG>>>(X, INPUT, W1r, b1r, Z);
    // 4) layer-1 recurrence v8.2 (fast epilogue)   <-- ncu capture slot
    rec_layer<1><<<dim3(64, 2), 384, SMEM_REC>>>(U1T, Z, H1, bar1);
    // 5) Z = H1[1..64] @ W2r^T + b2r  (K=1024, KT=32)
    mma_gemm_bias<32><<<dim3(G4 / 128, SB / 128), 256, SMEM_BIG>>>(H1 + BH, HIDDEN, W2r, b2r, Z);
    // 6) layer-2 recurrence v8.2
    rec_layer<0><<<dim3(64, 2), 384, SMEM_REC>>>(U2T, Z, h2, bar2);
    // 7) out = h2[0] @ Wo + bo
    final_proj_kernel<<<dim3((CLASSES + 63) / 64, BATCH / 64), 256>>>(h2, Wo, bo, out);
}